// round 8
// baseline (speedup 1.0000x reference)
#include <cuda_runtime.h>
#include <cuda_bf16.h>
#include <math.h>
#include <stddef.h>
#include <stdint.h>

// ---------------------------------------------------------------------------
// Problem constants
// ---------------------------------------------------------------------------
#define B_TOK   16384
#define D_IN    512
#define D_OUT   64
#define H1      64
#define H2      32
#define GH      32
#define NEXP    6
#define NCAT    480
#define NCATP   512
#define LN_EPS  1e-5f

// ---------------------------------------------------------------------------
// Device scratch
// ---------------------------------------------------------------------------
__device__ __align__(16) __nv_bfloat16 g_vhi[(size_t)B_TOK * D_IN];
__device__ __align__(16) __nv_bfloat16 g_vlo[(size_t)B_TOK * D_IN];
__device__ __align__(16) __nv_bfloat16 g_wthi[NCATP * D_IN];   // [n][k]
__device__ __align__(16) __nv_bfloat16 g_wtlo[NCATP * D_IN];
__device__ float g_bc[NCATP];
__device__ __align__(16) float g_HT[(size_t)NCATP * B_TOK];    // H transposed [col][token]

__device__ __forceinline__ uint32_t smem_u32(const void* p) {
    uint32_t a;
    asm("{ .reg .u64 t; cvta.to.shared.u64 t, %1; cvt.u32.u64 %0, t; }" : "=r"(a) : "l"(p));
    return a;
}

// ---------------------------------------------------------------------------
// Kernel: convert v -> bf16 hi/lo (error-free split)
// ---------------------------------------------------------------------------
__global__ __launch_bounds__(256) void conv_v_kernel(const float* __restrict__ v) {
    size_t i = ((size_t)blockIdx.x * 256 + threadIdx.x) * 4;
    float4 x = *(const float4*)(v + i);
    __nv_bfloat16 h0 = __float2bfloat16_rn(x.x), h1 = __float2bfloat16_rn(x.y);
    __nv_bfloat16 h2 = __float2bfloat16_rn(x.z), h3 = __float2bfloat16_rn(x.w);
    __nv_bfloat16 l0 = __float2bfloat16_rn(x.x - __bfloat162float(h0));
    __nv_bfloat16 l1 = __float2bfloat16_rn(x.y - __bfloat162float(h1));
    __nv_bfloat16 l2 = __float2bfloat16_rn(x.z - __bfloat162float(h2));
    __nv_bfloat16 l3 = __float2bfloat16_rn(x.w - __bfloat162float(h3));
    __nv_bfloat162* ph = (__nv_bfloat162*)(g_vhi + i);
    __nv_bfloat162* pl = (__nv_bfloat162*)(g_vlo + i);
    ph[0] = __nv_bfloat162(h0, h1); ph[1] = __nv_bfloat162(h2, h3);
    pl[0] = __nv_bfloat162(l0, l1); pl[1] = __nv_bfloat162(l2, l3);
}

// ---------------------------------------------------------------------------
// Kernel: pack transposed layer-1 weights [n][k] bf16 hi/lo + bias (padded)
// ---------------------------------------------------------------------------
__global__ __launch_bounds__(256) void pack_w_kernel(
    const float* __restrict__ sw1, const float* __restrict__ sb1,
    const float* __restrict__ gw1, const float* __restrict__ gb1,
    const float* __restrict__ sgw1, const float* __restrict__ sgb1,
    const float* __restrict__ ggw1, const float* __restrict__ ggb1) {
    int idx = blockIdx.x * 256 + threadIdx.x;   // over 512*512
    int n = idx >> 9, k = idx & 511;
    float w = 0.f;
    if (n < 384) {
        int e = n >> 6, j = n & 63;
        w = (e < 2) ? sw1[((size_t)e * D_IN + k) * 64 + j]
                    : gw1[((size_t)(e - 2) * D_IN + k) * 64 + j];
    } else if (n < 480) {
        int m = n - 384, s = m >> 5, j = m & 31;
        w = (s == 0) ? sgw1[k * 32 + j]
                     : ggw1[((size_t)(s - 1) * D_IN + k) * 32 + j];
    }
    __nv_bfloat16 hi = __float2bfloat16_rn(w);
    g_wthi[idx] = hi;
    g_wtlo[idx] = __float2bfloat16_rn(w - __bfloat162float(hi));
    if (idx < NCATP) {
        float b = 0.f;
        if (idx < 384) {
            int e = idx >> 6, j = idx & 63;
            b = (e < 2) ? sb1[e * 64 + j] : gb1[(e - 2) * 64 + j];
        } else if (idx < 480) {
            int m = idx - 384, s = m >> 5, j = m & 31;
            b = (s == 0) ? sgb1[j] : ggb1[(s - 1) * GH + j];
        }
        g_bc[idx] = b;
    }
}

// ---------------------------------------------------------------------------
// Kernel: H^T = silu(v @ W + b)^T via mma.sync bf16 split (3 passes),
// 2-stage cp.async pipeline, K chunks of 32. (unchanged from R7)
// ---------------------------------------------------------------------------
#define KCH2    32
#define RS2     80
#define OPB     (128 * RS2)
#define STAGE_B (4 * OPB)
#define SMO_BIAS (2 * STAGE_B)
#define GEMM_SMEM (SMO_BIAS + 512)
#define STG_STRIDE 136
#define NCHUNK  (D_IN / KCH2)

#define CPASYNC16(dst, src) \
    asm volatile("cp.async.cg.shared.global [%0], [%1], 16;" :: "r"(dst), "l"(src))

__device__ __forceinline__ void ldsm_x4(uint32_t* r, uint32_t a) {
    asm volatile("ldmatrix.sync.aligned.m8n8.x4.shared.b16 {%0,%1,%2,%3}, [%4];"
                 : "=r"(r[0]), "=r"(r[1]), "=r"(r[2]), "=r"(r[3]) : "r"(a));
}
__device__ __forceinline__ void mma_bf16(float* c, const uint32_t* a, uint32_t b0, uint32_t b1) {
    asm volatile(
        "mma.sync.aligned.m16n8k16.row.col.f32.bf16.bf16.f32 "
        "{%0,%1,%2,%3}, {%4,%5,%6,%7}, {%8,%9}, {%0,%1,%2,%3};"
        : "+f"(c[0]), "+f"(c[1]), "+f"(c[2]), "+f"(c[3])
        : "r"(a[0]), "r"(a[1]), "r"(a[2]), "r"(a[3]), "r"(b0), "r"(b1));
}

__global__ void __launch_bounds__(256, 2) gemm1_mma_kernel() {
    extern __shared__ char smem[];
    const uint32_t sb = smem_u32(smem);
    const int tid  = threadIdx.x;
    const int lane = tid & 31;
    const int warp = tid >> 5;
    const int wm = warp >> 2;
    const int wn = warp & 3;
    const int bm = blockIdx.y * 128;
    const int bn = blockIdx.x * 128;

    if (tid < 128) ((float*)(smem + SMO_BIAS))[tid] = g_bc[bn + tid];

    const int r0 = tid >> 2, r1 = (tid + 256) >> 2;
    const int s4 = (tid & 3) * 16;

    const int mi = lane >> 3;
    const int a_row = (lane & 7) + ((mi & 1) << 3);
    const int a_kb  = (mi >= 2) ? 16 : 0;
    const int b_row = (lane & 7) + ((mi >= 2) ? 8 : 0);
    const int b_kb  = (mi & 1) ? 16 : 0;

    float acc[4][4][4];
#pragma unroll
    for (int i = 0; i < 4; i++)
#pragma unroll
        for (int j = 0; j < 4; j++)
#pragma unroll
            for (int u = 0; u < 4; u++) acc[i][j][u] = 0.f;

    auto load_chunk = [&](int ch, int stg) {
        const int k0 = ch * KCH2;
        const uint32_t base = sb + stg * STAGE_B;
        const __nv_bfloat16* sa0 = g_vhi  + (size_t)(bm + r0) * D_IN + k0 + (s4 >> 1);
        const __nv_bfloat16* sa1 = g_vhi  + (size_t)(bm + r1) * D_IN + k0 + (s4 >> 1);
        const __nv_bfloat16* sb0 = g_wthi + (size_t)(bn + r0) * D_IN + k0 + (s4 >> 1);
        const __nv_bfloat16* sb1_ = g_wthi + (size_t)(bn + r1) * D_IN + k0 + (s4 >> 1);
        uint32_t d0 = r0 * RS2 + s4, d1 = r1 * RS2 + s4;
        CPASYNC16(base + 0 * OPB + d0, sa0);
        CPASYNC16(base + 0 * OPB + d1, sa1);
        CPASYNC16(base + 1 * OPB + d0, sa0 + (g_vlo - g_vhi));
        CPASYNC16(base + 1 * OPB + d1, sa1 + (g_vlo - g_vhi));
        CPASYNC16(base + 2 * OPB + d0, sb0);
        CPASYNC16(base + 2 * OPB + d1, sb1_);
        CPASYNC16(base + 3 * OPB + d0, sb0 + (g_wtlo - g_wthi));
        CPASYNC16(base + 3 * OPB + d1, sb1_ + (g_wtlo - g_wthi));
    };

    load_chunk(0, 0);
    asm volatile("cp.async.commit_group;");

    for (int ch = 0; ch < NCHUNK; ch++) {
        const int cur = ch & 1;
        if (ch + 1 < NCHUNK) {
            load_chunk(ch + 1, (ch + 1) & 1);
            asm volatile("cp.async.commit_group;");
            asm volatile("cp.async.wait_group 1;");
        } else {
            asm volatile("cp.async.wait_group 0;");
        }
        __syncthreads();

        const uint32_t stgb = sb + cur * STAGE_B;
        const uint32_t aAddr0 = stgb + 0 * OPB + (wm * 64 + a_row) * RS2 + a_kb;
        const uint32_t alAdd  = 1 * OPB;
        const uint32_t bAddr0 = stgb + 2 * OPB + (wn * 32 + b_row) * RS2 + b_kb;
        const uint32_t blAdd  = 1 * OPB;

#pragma unroll
        for (int kt = 0; kt < 2; kt++) {
            const uint32_t ka = kt * 32;
            uint32_t ah[4][4], al[4][4], bh[2][4], bl[2][4];
#pragma unroll
            for (int mt = 0; mt < 4; mt++)
                ldsm_x4(ah[mt], aAddr0 + mt * (16 * RS2) + ka);
#pragma unroll
            for (int h = 0; h < 2; h++)
                ldsm_x4(bh[h], bAddr0 + h * (16 * RS2) + ka);
#pragma unroll
            for (int mt = 0; mt < 4; mt++)
#pragma unroll
                for (int nt = 0; nt < 4; nt++)
                    mma_bf16(acc[mt][nt], ah[mt], bh[nt >> 1][(nt & 1) * 2], bh[nt >> 1][(nt & 1) * 2 + 1]);
#pragma unroll
            for (int h = 0; h < 2; h++)
                ldsm_x4(bl[h], bAddr0 + blAdd + h * (16 * RS2) + ka);
#pragma unroll
            for (int mt = 0; mt < 4; mt++)
#pragma unroll
                for (int nt = 0; nt < 4; nt++)
                    mma_bf16(acc[mt][nt], ah[mt], bl[nt >> 1][(nt & 1) * 2], bl[nt >> 1][(nt & 1) * 2 + 1]);
#pragma unroll
            for (int mt = 0; mt < 4; mt++)
                ldsm_x4(al[mt], aAddr0 + alAdd + mt * (16 * RS2) + ka);
#pragma unroll
            for (int mt = 0; mt < 4; mt++)
#pragma unroll
                for (int nt = 0; nt < 4; nt++)
                    mma_bf16(acc[mt][nt], al[mt], bh[nt >> 1][(nt & 1) * 2], bh[nt >> 1][(nt & 1) * 2 + 1]);
        }
        __syncthreads();
    }

    // Epilogue: bias + silu -> smem stage [col][row] -> coalesced g_HT writes
    {
        float* stg = (float*)smem;
        const float* bias = (const float*)(smem + SMO_BIAS);
#pragma unroll
        for (int mt = 0; mt < 4; mt++) {
#pragma unroll
            for (int nt = 0; nt < 4; nt++) {
#pragma unroll
                for (int u = 0; u < 4; u++) {
                    int row = wm * 64 + mt * 16 + (lane >> 2) + ((u >> 1) << 3);
                    int col = wn * 32 + nt * 8 + 2 * (lane & 3) + (u & 1);
                    float x = acc[mt][nt][u] + bias[col];
                    stg[col * STG_STRIDE + row] = x / (1.f + __expf(-x));
                }
            }
        }
        __syncthreads();
#pragma unroll
        for (int cl = 0; cl < 16; cl++) {
            int col = warp * 16 + cl;
            int gc = bn + col;
            if (gc < NCAT) {
                float4 val = *(float4*)&stg[col * STG_STRIDE + lane * 4];
                *(float4*)(g_HT + (size_t)gc * B_TOK + bm + lane * 4) = val;
            }
        }
    }
}

// ---------------------------------------------------------------------------
// Kernel: tail6 — slot-per-CTA, 256 threads, 64 tokens, 4 threads/token.
// h1 both experts + weights staged; h2 exchanged through padded smem;
// z in registers across experts; direct store. grid (B/64, 3).
// ---------------------------------------------------------------------------
// smem floats:
#define T6_H1   0                         // 128*64 = 8192 (both experts)
#define T6_HX   8192                      // 2112 : gate stage [32][64] then h2s [64][33]
#define T6_W2   10304                     // 2*2048
#define T6_W3   14400                     // 2*2048
#define T6_B2   18496                     // 2*32
#define T6_B3   18560                     // 2*64
#define T6_GM   18688                     // 2*64
#define T6_BT   18816                     // 2*64
#define T6_GW   18944                     // 64
#define T6_GB   19008                     // 2
#define T6_FLOATS 19010
#define T6_SMEM (T6_FLOATS * 4)

__global__ void __launch_bounds__(256, 3) tail6_kernel(
    const float* __restrict__ sw2, const float* __restrict__ sb2,
    const float* __restrict__ sw3, const float* __restrict__ sb3,
    const float* __restrict__ sgam, const float* __restrict__ sbet,
    const float* __restrict__ sgw2, const float* __restrict__ sgb2,
    const float* __restrict__ gw2, const float* __restrict__ gb2,
    const float* __restrict__ gw3, const float* __restrict__ gb3,
    const float* __restrict__ ggam, const float* __restrict__ gbet,
    const float* __restrict__ ggw2, const float* __restrict__ ggb2,
    float* __restrict__ out) {
    extern __shared__ float sm[];
    const unsigned FULL = 0xffffffffu;

    const int p    = blockIdx.y;          // 0=group0(e2,3) 1=group1(e4,5) 2=shared(e0,1)
    const int tid  = threadIdx.x;
    const int quarter = tid & 3;
    const int ltok = tid >> 2;            // 0..63
    const int t0   = blockIdx.x * 64;
    const int tok  = t0 + ltok;
    const int e_base = (p == 2) ? 0 : ((p == 0) ? 2 : 4);
    const int gslot  = (p == 2) ? 0 : (p + 1);

    // --- stage h1 rows for BOTH experts: 128 rows x 64 tokens ---
    {
        const float* src = g_HT + (size_t)(e_base * 64) * B_TOK + t0;
#pragma unroll
        for (int k = 0; k < 8; k++) {
            int lin = tid + k * 256;          // 0..2047 float4
            int row = lin >> 4, q = lin & 15;
            float4 val = *(const float4*)(src + (size_t)row * B_TOK + q * 4);
            *(float4*)&sm[T6_H1 + row * 64 + q * 4] = val;
        }
    }
    // --- stage gate rows [32][64] into T6_HX ---
    {
        const float* src = g_HT + (size_t)(384 + gslot * 32) * B_TOK + t0;
#pragma unroll
        for (int k = 0; k < 2; k++) {
            int lin = tid + k * 256;          // 0..511 float4
            int row = lin >> 4, q = lin & 15;
            float4 val = *(const float4*)(src + (size_t)row * B_TOK + q * 4);
            *(float4*)&sm[T6_HX + row * 64 + q * 4] = val;
        }
    }
    // --- stage weights/params for both experts ---
#pragma unroll
    for (int s = 0; s < 2; s++) {
        const int e = e_base + s;
        const float* w2src = (e < 2) ? (sw2 + (size_t)e * 2048) : (gw2 + (size_t)(e - 2) * 2048);
        const float* w3src = (e < 2) ? (sw3 + (size_t)e * 2048) : (gw3 + (size_t)(e - 2) * 2048);
        for (int i = tid; i < 2048; i += 256) {
            sm[T6_W2 + s * 2048 + i] = w2src[i];
            sm[T6_W3 + s * 2048 + i] = w3src[i];
        }
        if (tid < H2) sm[T6_B2 + s * 32 + tid] = (e < 2) ? sb2[e * 32 + tid] : gb2[(e - 2) * 32 + tid];
        if (tid < D_OUT) {
            sm[T6_B3 + s * 64 + tid] = (e < 2) ? sb3[e * 64 + tid]  : gb3[(e - 2) * 64 + tid];
            sm[T6_GM + s * 64 + tid] = (e < 2) ? sgam[e * 64 + tid] : ggam[(e - 2) * 64 + tid];
            sm[T6_BT + s * 64 + tid] = (e < 2) ? sbet[e * 64 + tid] : gbet[(e - 2) * 64 + tid];
        }
    }
    if (tid < 64) sm[T6_GW + tid] = (gslot == 0) ? sgw2[tid] : ggw2[(gslot - 1) * 64 + tid];
    if (tid < 2)  sm[T6_GB + tid] = (gslot == 0) ? sgb2[tid] : ggb2[(gslot - 1) * 2 + tid];
    __syncthreads();

    // --- gate softmax from staged rows (all quartet threads identical) ---
    float wgate2[2];
    {
        float l0 = sm[T6_GB + 0], l1 = sm[T6_GB + 1];
#pragma unroll 8
        for (int i = 0; i < GH; i++) {
            float hg = sm[T6_HX + i * 64 + ltok];
            l0 += hg * sm[T6_GW + i * 2];
            l1 += hg * sm[T6_GW + i * 2 + 1];
        }
        float mx = fmaxf(l0, l1);
        float ea = __expf(l0 - mx), eb = __expf(l1 - mx);
        float inv_s = 1.f / (ea + eb);
        wgate2[0] = ea * inv_s;
        wgate2[1] = eb * inv_s;
    }

    float z[16];

#pragma unroll
    for (int s = 0; s < 2; s++) {
        __syncthreads();   // s=0: gate reads done before h2s overwrite; s=1: layer3 reads done

        // layer 2: this quarter's 8 h2 dims
        const float* h1b = sm + T6_H1 + s * (64 * 64);
        const float* w2b = sm + T6_W2 + s * 2048 + quarter * 8;
        float h2[8];
        {
            const float* b2 = sm + T6_B2 + s * 32 + quarter * 8;
#pragma unroll
            for (int j = 0; j < 8; j++) h2[j] = b2[j];
        }
#pragma unroll 8
        for (int i = 0; i < H1; i++) {
            float a = h1b[i * 64 + ltok];
            const float4* w4 = (const float4*)(w2b + i * 32);
            float4 w0 = w4[0], w1 = w4[1];
            h2[0] += a * w0.x; h2[1] += a * w0.y; h2[2] += a * w0.z; h2[3] += a * w0.w;
            h2[4] += a * w1.x; h2[5] += a * w1.y; h2[6] += a * w1.z; h2[7] += a * w1.w;
        }
#pragma unroll
        for (int j = 0; j < 8; j++) h2[j] = h2[j] / (1.f + __expf(-h2[j]));

        // write h2 to padded smem [tok][33]
        {
            float* dst = sm + T6_HX + ltok * 33 + quarter * 8;
#pragma unroll
            for (int j = 0; j < 8; j++) dst[j] = h2[j];
        }
        __syncthreads();

        // layer 3: this quarter's 16 output dims
        float o[16];
        {
            const float* b3 = sm + T6_B3 + s * 64 + quarter * 16;
#pragma unroll
            for (int j = 0; j < 16; j++) o[j] = b3[j];
        }
        const float* h2row = sm + T6_HX + ltok * 33;
        const float* w3b = sm + T6_W3 + s * 2048 + quarter * 16;
#pragma unroll 8
        for (int k = 0; k < H2; k++) {
            float h = h2row[k];
            const float4* w4 = (const float4*)(w3b + k * 64);
            float4 w0 = w4[0], w1 = w4[1], w2_ = w4[2], w3_ = w4[3];
            o[0]  += h * w0.x;  o[1]  += h * w0.y;  o[2]  += h * w0.z;  o[3]  += h * w0.w;
            o[4]  += h * w1.x;  o[5]  += h * w1.y;  o[6]  += h * w1.z;  o[7]  += h * w1.w;
            o[8]  += h * w2_.x; o[9]  += h * w2_.y; o[10] += h * w2_.z; o[11] += h * w2_.w;
            o[12] += h * w3_.x; o[13] += h * w3_.y; o[14] += h * w3_.z; o[15] += h * w3_.w;
        }

        // LayerNorm across the quartet (shfl_xor 1 then 2)
        float s1 = 0.f;
#pragma unroll
        for (int j = 0; j < 16; j++) s1 += o[j];
        s1 += __shfl_xor_sync(FULL, s1, 1);
        s1 += __shfl_xor_sync(FULL, s1, 2);
        float mu = s1 * (1.f / 64.f);
        float s2 = 0.f;
#pragma unroll
        for (int j = 0; j < 16; j++) { float d = o[j] - mu; s2 += d * d; }
        s2 += __shfl_xor_sync(FULL, s2, 1);
        s2 += __shfl_xor_sync(FULL, s2, 2);
        float x = s2 * (1.f / 64.f) + LN_EPS;
        float rinv = rsqrtf(x);
        rinv = rinv * (1.5f - 0.5f * x * rinv * rinv);

        const float wg = wgate2[s];
        const float* gm = sm + T6_GM + s * 64 + quarter * 16;
        const float* bt = sm + T6_BT + s * 64 + quarter * 16;
        if (s == 0) {
#pragma unroll
            for (int j = 0; j < 16; j++)
                z[j] = wg * (gm[j] * (o[j] - mu) * rinv + bt[j]);
        } else {
#pragma unroll
            for (int j = 0; j < 16; j++)
                z[j] += wg * (gm[j] * (o[j] - mu) * rinv + bt[j]);
        }
    }

    // direct store: out[p][tok][quarter*16 .. +15]
    float* obase = out + ((size_t)p * B_TOK + tok) * D_OUT + quarter * 16;
#pragma unroll
    for (int j4 = 0; j4 < 4; j4++) {
        float4 y;
        y.x = z[j4 * 4 + 0]; y.y = z[j4 * 4 + 1];
        y.z = z[j4 * 4 + 2]; y.w = z[j4 * 4 + 3];
        *(float4*)(obase + j4 * 4) = y;
    }
}

// ---------------------------------------------------------------------------
// Launch
// ---------------------------------------------------------------------------
extern "C" void kernel_launch(void* const* d_in, const int* in_sizes, int n_in,
                              void* d_out, int out_size) {
    (void)in_sizes; (void)n_in; (void)out_size;
    const float* v    = (const float*)d_in[0];
    const float* sw1  = (const float*)d_in[1];
    const float* sb1  = (const float*)d_in[2];
    const float* sw2  = (const float*)d_in[3];
    const float* sb2  = (const float*)d_in[4];
    const float* sw3  = (const float*)d_in[5];
    const float* sb3  = (const float*)d_in[6];
    const float* sgam = (const float*)d_in[7];
    const float* sbet = (const float*)d_in[8];
    const float* sgw1 = (const float*)d_in[9];
    const float* sgb1 = (const float*)d_in[10];
    const float* sgw2 = (const float*)d_in[11];
    const float* sgb2 = (const float*)d_in[12];
    const float* gw1  = (const float*)d_in[13];
    const float* gb1  = (const float*)d_in[14];
    const float* gw2  = (const float*)d_in[15];
    const float* gb2  = (const float*)d_in[16];
    const float* gw3  = (const float*)d_in[17];
    const float* gb3  = (const float*)d_in[18];
    const float* ggam = (const float*)d_in[19];
    const float* gbet = (const float*)d_in[20];
    const float* ggw1 = (const float*)d_in[21];
    const float* ggb1 = (const float*)d_in[22];
    const float* ggw2 = (const float*)d_in[23];
    const float* ggb2 = (const float*)d_in[24];
    float* out = (float*)d_out;

    conv_v_kernel<<<(B_TOK * D_IN / 4 + 255) / 256, 256>>>(v);
    pack_w_kernel<<<(NCATP * D_IN + 255) / 256, 256>>>(sw1, sb1, gw1, gb1, sgw1, sgb1, ggw1, ggb1);

    cudaFuncSetAttribute(gemm1_mma_kernel, cudaFuncAttributeMaxDynamicSharedMemorySize, GEMM_SMEM);
    dim3 g1(NCATP / 128, B_TOK / 128);
    gemm1_mma_kernel<<<g1, 256, GEMM_SMEM>>>();

    cudaFuncSetAttribute(tail6_kernel, cudaFuncAttributeMaxDynamicSharedMemorySize, T6_SMEM);
    dim3 g2(B_TOK / 64, 3);
    tail6_kernel<<<g2, 256, T6_SMEM>>>(sw2, sb2, sw3, sb3, sgam, sbet, sgw2, sgb2,
                                       gw2, gb2, gw3, gb3, ggam, gbet, ggw2, ggb2, out);
}

// round 11
// speedup vs baseline: 1.3752x; 1.3752x over previous
#include <cuda_runtime.h>
#include <cuda_bf16.h>
#include <math.h>
#include <stddef.h>
#include <stdint.h>

// ---------------------------------------------------------------------------
// Problem constants
// ---------------------------------------------------------------------------
#define B_TOK   16384
#define D_IN    512
#define D_OUT   64
#define H1      64
#define H2      32
#define GH      32
#define NEXP    6
#define NCAT    480
#define NCATP   512
#define LN_EPS  1e-5f

// ---------------------------------------------------------------------------
// Device scratch
// ---------------------------------------------------------------------------
__device__ __align__(16) __nv_bfloat16 g_vhi[(size_t)B_TOK * D_IN];
__device__ __align__(16) __nv_bfloat16 g_vlo[(size_t)B_TOK * D_IN];
__device__ __align__(16) __nv_bfloat16 g_wthi[NCATP * D_IN];   // [n][k]
__device__ __align__(16) __nv_bfloat16 g_wtlo[NCATP * D_IN];
__device__ float g_bc[NCATP];
__device__ __align__(16) float g_HT[(size_t)NCATP * B_TOK];    // H transposed [col][token]

__device__ __forceinline__ uint32_t smem_u32(const void* p) {
    uint32_t a;
    asm("{ .reg .u64 t; cvta.to.shared.u64 t, %1; cvt.u32.u64 %0, t; }" : "=r"(a) : "l"(p));
    return a;
}

// ---------------------------------------------------------------------------
// Kernel: prep = conv_v (blocks 0..8191) + pack_w (blocks 8192..9215)
// ---------------------------------------------------------------------------
#define CONV_BLOCKS 8192
__global__ __launch_bounds__(256) void prep_kernel(
    const float* __restrict__ v,
    const float* __restrict__ sw1, const float* __restrict__ sb1,
    const float* __restrict__ gw1, const float* __restrict__ gb1,
    const float* __restrict__ sgw1, const float* __restrict__ sgb1,
    const float* __restrict__ ggw1, const float* __restrict__ ggb1) {
    if (blockIdx.x < CONV_BLOCKS) {
        size_t i = ((size_t)blockIdx.x * 256 + threadIdx.x) * 4;
        float4 x = *(const float4*)(v + i);
        __nv_bfloat16 h0 = __float2bfloat16_rn(x.x), h1 = __float2bfloat16_rn(x.y);
        __nv_bfloat16 h2 = __float2bfloat16_rn(x.z), h3 = __float2bfloat16_rn(x.w);
        __nv_bfloat16 l0 = __float2bfloat16_rn(x.x - __bfloat162float(h0));
        __nv_bfloat16 l1 = __float2bfloat16_rn(x.y - __bfloat162float(h1));
        __nv_bfloat16 l2 = __float2bfloat16_rn(x.z - __bfloat162float(h2));
        __nv_bfloat16 l3 = __float2bfloat16_rn(x.w - __bfloat162float(h3));
        __nv_bfloat162* ph = (__nv_bfloat162*)(g_vhi + i);
        __nv_bfloat162* pl = (__nv_bfloat162*)(g_vlo + i);
        ph[0] = __nv_bfloat162(h0, h1); ph[1] = __nv_bfloat162(h2, h3);
        pl[0] = __nv_bfloat162(l0, l1); pl[1] = __nv_bfloat162(l2, l3);
    } else {
        int idx = (blockIdx.x - CONV_BLOCKS) * 256 + threadIdx.x;   // over 512*512
        int n = idx >> 9, k = idx & 511;
        float w = 0.f;
        if (n < 384) {
            int e = n >> 6, j = n & 63;
            w = (e < 2) ? sw1[((size_t)e * D_IN + k) * 64 + j]
                        : gw1[((size_t)(e - 2) * D_IN + k) * 64 + j];
        } else if (n < 480) {
            int m = n - 384, s = m >> 5, j = m & 31;
            w = (s == 0) ? sgw1[k * 32 + j]
                         : ggw1[((size_t)(s - 1) * D_IN + k) * 32 + j];
        }
        __nv_bfloat16 hi = __float2bfloat16_rn(w);
        g_wthi[idx] = hi;
        g_wtlo[idx] = __float2bfloat16_rn(w - __bfloat162float(hi));
        if (idx < NCATP) {
            float b = 0.f;
            if (idx < 384) {
                int e = idx >> 6, j = idx & 63;
                b = (e < 2) ? sb1[e * 64 + j] : gb1[(e - 2) * 64 + j];
            } else if (idx < 480) {
                int m = idx - 384, s = m >> 5, j = m & 31;
                b = (s == 0) ? sgb1[j] : ggb1[(s - 1) * GH + j];
            }
            g_bc[idx] = b;
        }
    }
}

// ---------------------------------------------------------------------------
// Kernel: H^T = silu(v @ W + b)^T via mma.sync bf16 split (3 passes),
// 3-stage cp.async pipeline (prefetch distance 2), K chunks of 32,
// ONE __syncthreads per chunk. CTA 128x128, warps 2(M)x4(N).
// SMEM rows: 64B natural stride with XOR swizzle seg' = seg ^ ((row>>1)&3)
// -> 16B-aligned (ldmatrix + cp.async.16 legal) AND conflict-free.
// ---------------------------------------------------------------------------
#define KCH2    32
#define OPB     (128 * 64)                  // 8192 per operand per stage
#define STAGE_B (4 * OPB)                   // 32768
#define NSTAGE  3
#define SMO_BIAS (NSTAGE * STAGE_B)         // 98304
#define GEMM_SMEM (SMO_BIAS + 512)          // 98816
#define STG_STRIDE 136                      // floats, epilogue stage [col][row]
#define NCHUNK  (D_IN / KCH2)               // 16

#define CPASYNC16(dst, src) \
    asm volatile("cp.async.cg.shared.global [%0], [%1], 16;" :: "r"(dst), "l"(src))

__device__ __forceinline__ void ldsm_x4(uint32_t* r, uint32_t a) {
    asm volatile("ldmatrix.sync.aligned.m8n8.x4.shared.b16 {%0,%1,%2,%3}, [%4];"
                 : "=r"(r[0]), "=r"(r[1]), "=r"(r[2]), "=r"(r[3]) : "r"(a));
}
__device__ __forceinline__ void mma_bf16(float* c, const uint32_t* a, uint32_t b0, uint32_t b1) {
    asm volatile(
        "mma.sync.aligned.m16n8k16.row.col.f32.bf16.bf16.f32 "
        "{%0,%1,%2,%3}, {%4,%5,%6,%7}, {%8,%9}, {%0,%1,%2,%3};"
        : "+f"(c[0]), "+f"(c[1]), "+f"(c[2]), "+f"(c[3])
        : "r"(a[0]), "r"(a[1]), "r"(a[2]), "r"(a[3]), "r"(b0), "r"(b1));
}

__global__ void __launch_bounds__(256, 2) gemm1_mma_kernel() {
    extern __shared__ char smem[];
    const uint32_t sb = smem_u32(smem);
    const int tid  = threadIdx.x;
    const int lane = tid & 31;
    const int warp = tid >> 5;
    const int wm = warp >> 2;
    const int wn = warp & 3;
    const int bm = blockIdx.y * 128;
    const int bn = blockIdx.x * 128;

    if (tid < 128) ((float*)(smem + SMO_BIAS))[tid] = g_bc[bn + tid];

    // cp.async geometry: per operand 128 rows x 4 segs of 16B; 2 (row,seg)
    // pairs per thread. seg' = seg ^ ((row>>1)&3).
    const int r0 = tid >> 2, r1 = r0 + 64;
    const int seg = tid & 3;
    const uint32_t d0 = (uint32_t)(r0 * 64 + ((seg ^ ((r0 >> 1) & 3)) << 4));
    const uint32_t d1 = (uint32_t)(r1 * 64 + ((seg ^ ((r1 >> 1) & 3)) << 4));
    const int selem = seg * 8;              // bf16 elements into the 64B k-chunk

    // ldmatrix lane geometry
    const int mi = lane >> 3;
    const int a_row = (lane & 7) + ((mi & 1) << 3);
    const int akb4  = (mi >= 2) ? 1 : 0;    // k 16B-seg within ldsm
    const int b_row = (lane & 7) + ((mi >= 2) ? 8 : 0);
    const int bkb4  = (mi & 1) ? 1 : 0;
    const int arsw  = (a_row >> 1) & 3;     // swizzle term (mt-invariant: mt*16 keeps bits1-2)
    const int brsw  = (b_row >> 1) & 3;

    float acc[4][4][4];
#pragma unroll
    for (int i = 0; i < 4; i++)
#pragma unroll
        for (int j = 0; j < 4; j++)
#pragma unroll
            for (int u = 0; u < 4; u++) acc[i][j][u] = 0.f;

    auto load_chunk = [&](int ch, int stg) {
        const int k0 = ch * KCH2;
        const uint32_t base = sb + stg * STAGE_B;
        const __nv_bfloat16* sa0 = g_vhi  + (size_t)(bm + r0) * D_IN + k0 + selem;
        const __nv_bfloat16* sa1 = g_vhi  + (size_t)(bm + r1) * D_IN + k0 + selem;
        const __nv_bfloat16* sb0 = g_wthi + (size_t)(bn + r0) * D_IN + k0 + selem;
        const __nv_bfloat16* sb1_ = g_wthi + (size_t)(bn + r1) * D_IN + k0 + selem;
        const ptrdiff_t dlo = g_vlo - g_vhi;
        const ptrdiff_t dwl = g_wtlo - g_wthi;
        CPASYNC16(base + 0 * OPB + d0, sa0);
        CPASYNC16(base + 0 * OPB + d1, sa1);
        CPASYNC16(base + 1 * OPB + d0, sa0 + dlo);
        CPASYNC16(base + 1 * OPB + d1, sa1 + dlo);
        CPASYNC16(base + 2 * OPB + d0, sb0);
        CPASYNC16(base + 2 * OPB + d1, sb1_);
        CPASYNC16(base + 3 * OPB + d0, sb0 + dwl);
        CPASYNC16(base + 3 * OPB + d1, sb1_ + dwl);
    };

    // prologue: prefetch chunks 0 and 1
    load_chunk(0, 0);
    asm volatile("cp.async.commit_group;");
    load_chunk(1, 1);
    asm volatile("cp.async.commit_group;");

    for (int ch = 0; ch < NCHUNK; ch++) {
        if (ch < NCHUNK - 1) {
            asm volatile("cp.async.wait_group 1;");
        } else {
            asm volatile("cp.async.wait_group 0;");
        }
        __syncthreads();   // single barrier per chunk

        // prefetch chunk ch+2 into stage (ch+2)%3 — computed at ch-1, and the
        // barrier above guarantees all threads are past that compute.
        if (ch + 2 < NCHUNK) {
            load_chunk(ch + 2, (ch + 2) % NSTAGE);
            asm volatile("cp.async.commit_group;");
        }

        const uint32_t stgb  = sb + (ch % NSTAGE) * STAGE_B;
        const uint32_t aBase = stgb + 0 * OPB + (uint32_t)((wm * 64 + a_row) * 64);
        const uint32_t bBase = stgb + 2 * OPB + (uint32_t)((wn * 32 + b_row) * 64);

#pragma unroll
        for (int kt = 0; kt < 2; kt++) {
            const uint32_t aoff = (uint32_t)(((kt * 2 + akb4) ^ arsw) << 4);
            const uint32_t boff = (uint32_t)(((kt * 2 + bkb4) ^ brsw) << 4);
            uint32_t ah[4][4], al[4][4], bh[2][4], bl[2][4];
#pragma unroll
            for (int mt = 0; mt < 4; mt++)
                ldsm_x4(ah[mt], aBase + mt * 1024 + aoff);
#pragma unroll
            for (int h = 0; h < 2; h++)
                ldsm_x4(bh[h], bBase + h * 1024 + boff);
#pragma unroll
            for (int mt = 0; mt < 4; mt++)
#pragma unroll
                for (int nt = 0; nt < 4; nt++)
                    mma_bf16(acc[mt][nt], ah[mt], bh[nt >> 1][(nt & 1) * 2], bh[nt >> 1][(nt & 1) * 2 + 1]);
#pragma unroll
            for (int h = 0; h < 2; h++)
                ldsm_x4(bl[h], bBase + OPB + h * 1024 + boff);
#pragma unroll
            for (int mt = 0; mt < 4; mt++)
#pragma unroll
                for (int nt = 0; nt < 4; nt++)
                    mma_bf16(acc[mt][nt], ah[mt], bl[nt >> 1][(nt & 1) * 2], bl[nt >> 1][(nt & 1) * 2 + 1]);
#pragma unroll
            for (int mt = 0; mt < 4; mt++)
                ldsm_x4(al[mt], aBase + OPB + mt * 1024 + aoff);
#pragma unroll
            for (int mt = 0; mt < 4; mt++)
#pragma unroll
                for (int nt = 0; nt < 4; nt++)
                    mma_bf16(acc[mt][nt], al[mt], bh[nt >> 1][(nt & 1) * 2], bh[nt >> 1][(nt & 1) * 2 + 1]);
        }
    }
    __syncthreads();

    // Epilogue: bias + silu -> smem stage [col][row] -> coalesced g_HT writes
    {
        float* stg = (float*)smem;
        const float* bias = (const float*)(smem + SMO_BIAS);
#pragma unroll
        for (int mt = 0; mt < 4; mt++) {
#pragma unroll
            for (int nt = 0; nt < 4; nt++) {
#pragma unroll
                for (int u = 0; u < 4; u++) {
                    int row = wm * 64 + mt * 16 + (lane >> 2) + ((u >> 1) << 3);
                    int col = wn * 32 + nt * 8 + 2 * (lane & 3) + (u & 1);
                    float x = acc[mt][nt][u] + bias[col];
                    stg[col * STG_STRIDE + row] = x / (1.f + __expf(-x));
                }
            }
        }
        __syncthreads();
#pragma unroll
        for (int cl = 0; cl < 16; cl++) {
            int col = warp * 16 + cl;
            int gc = bn + col;
            if (gc < NCAT) {
                float4 val = *(float4*)&stg[col * STG_STRIDE + lane * 4];
                *(float4*)(g_HT + (size_t)gc * B_TOK + bm + lane * 4) = val;
            }
        }
    }
}

// ---------------------------------------------------------------------------
// Kernel: tail5 — slot-per-CTA, 256 threads, 128 tokens, 2 threads/token.
// (verbatim — best known tail at 62.4us)
// ---------------------------------------------------------------------------
#define T5_H1   0                         // 2*64*128 = 16384
#define T5_W2   16384                     // 2*2048
#define T5_W3   20480                     // 2*2048
#define T5_B2   24576                     // 2*32
#define T5_B3   24640                     // 2*64
#define T5_GM   24768                     // 2*64
#define T5_BT   24896                     // 2*64
#define T5_GW   25024                     // 64
#define T5_GB   25088                     // 2
#define T5_FLOATS 25090
#define T5_SMEM (T5_FLOATS * 4)

__global__ void __launch_bounds__(256, 2) tail5_kernel(
    const float* __restrict__ sw2, const float* __restrict__ sb2,
    const float* __restrict__ sw3, const float* __restrict__ sb3,
    const float* __restrict__ sgam, const float* __restrict__ sbet,
    const float* __restrict__ sgw2, const float* __restrict__ sgb2,
    const float* __restrict__ gw2, const float* __restrict__ gb2,
    const float* __restrict__ gw3, const float* __restrict__ gb3,
    const float* __restrict__ ggam, const float* __restrict__ gbet,
    const float* __restrict__ ggw2, const float* __restrict__ ggb2,
    float* __restrict__ out) {
    extern __shared__ float sm[];
    const unsigned FULL = 0xffffffffu;

    const int p    = blockIdx.y;          // 0=group0(e2,3) 1=group1(e4,5) 2=shared(e0,1)
    const int tid  = threadIdx.x;
    const int half = tid & 1;
    const int ltok = tid >> 1;            // 0..127
    const int t0   = blockIdx.x * 128;
    const int tok  = t0 + ltok;
    const int e_base = (p == 2) ? 0 : ((p == 0) ? 2 : 4);
    const int gslot  = (p == 2) ? 0 : (p + 1);

    {
        const float* src = g_HT + (size_t)(e_base * 64) * B_TOK + t0;
#pragma unroll
        for (int k = 0; k < 16; k++) {
            int lin = tid + k * 256;          // 0..4095
            int row = lin >> 5, q = lin & 31;
            float4 val = *(const float4*)(src + (size_t)row * B_TOK + q * 4);
            *(float4*)&sm[T5_H1 + row * 128 + q * 4] = val;
        }
    }
#pragma unroll
    for (int s = 0; s < 2; s++) {
        const int e = e_base + s;
        const float* w2src = (e < 2) ? (sw2 + (size_t)e * 2048) : (gw2 + (size_t)(e - 2) * 2048);
        const float* w3src = (e < 2) ? (sw3 + (size_t)e * 2048) : (gw3 + (size_t)(e - 2) * 2048);
        for (int i = tid; i < 2048; i += 256) {
            sm[T5_W2 + s * 2048 + i] = w2src[i];
            sm[T5_W3 + s * 2048 + i] = w3src[i];
        }
        if (tid < H2) sm[T5_B2 + s * 32 + tid] = (e < 2) ? sb2[e * 32 + tid] : gb2[(e - 2) * 32 + tid];
        if (tid < D_OUT) {
            sm[T5_B3 + s * 64 + tid] = (e < 2) ? sb3[e * 64 + tid]  : gb3[(e - 2) * 64 + tid];
            sm[T5_GM + s * 64 + tid] = (e < 2) ? sgam[e * 64 + tid] : ggam[(e - 2) * 64 + tid];
            sm[T5_BT + s * 64 + tid] = (e < 2) ? sbet[e * 64 + tid] : gbet[(e - 2) * 64 + tid];
        }
    }
    if (tid < 64) sm[T5_GW + tid] = (gslot == 0) ? sgw2[tid] : ggw2[(gslot - 1) * 64 + tid];
    if (tid < 2)  sm[T5_GB + tid] = (gslot == 0) ? sgb2[tid] : ggb2[(gslot - 1) * 2 + tid];
    __syncthreads();

    float wgate2[2];
    {
        float l0 = sm[T5_GB + 0], l1 = sm[T5_GB + 1];
        const float* gbase = g_HT + (size_t)(384 + gslot * 32) * B_TOK + tok;
#pragma unroll 8
        for (int i = 0; i < GH; i++) {
            float hg = gbase[(size_t)i * B_TOK];
            l0 += hg * sm[T5_GW + i * 2];
            l1 += hg * sm[T5_GW + i * 2 + 1];
        }
        float mx = fmaxf(l0, l1);
        float ea = __expf(l0 - mx), eb = __expf(l1 - mx);
        float inv_s = 1.f / (ea + eb);
        wgate2[0] = ea * inv_s;
        wgate2[1] = eb * inv_s;
    }

    float z[32];

#pragma unroll
    for (int s = 0; s < 2; s++) {
        const float* h1b = sm + T5_H1 + s * 8192;
        const float* w2b = sm + T5_W2 + s * 2048 + half * 16;

        float h2[16];
        {
            const float* b2 = sm + T5_B2 + s * 32 + half * 16;
#pragma unroll
            for (int j = 0; j < 16; j++) h2[j] = b2[j];
        }
#pragma unroll 8
        for (int i = 0; i < H1; i++) {
            float a = h1b[i * 128 + ltok];
            const float4* w4 = (const float4*)(w2b + i * 32);
#pragma unroll
            for (int j4 = 0; j4 < 4; j4++) {
                float4 w = w4[j4];
                h2[j4 * 4 + 0] += a * w.x;
                h2[j4 * 4 + 1] += a * w.y;
                h2[j4 * 4 + 2] += a * w.z;
                h2[j4 * 4 + 3] += a * w.w;
            }
        }
#pragma unroll
        for (int j = 0; j < 16; j++) h2[j] = h2[j] / (1.f + __expf(-h2[j]));

        float hlo[16], hhi[16];
#pragma unroll
        for (int j = 0; j < 16; j++) {
            float other = __shfl_xor_sync(FULL, h2[j], 1);
            hlo[j] = half ? other : h2[j];
            hhi[j] = half ? h2[j] : other;
        }

        float o[32];
        {
            const float* b3 = sm + T5_B3 + s * 64 + half * 32;
#pragma unroll
            for (int j = 0; j < 32; j++) o[j] = b3[j];
        }
        const float* w3b = sm + T5_W3 + s * 2048 + half * 32;
#pragma unroll
        for (int k = 0; k < 16; k++) {
            float h = hlo[k];
            const float4* w4 = (const float4*)(w3b + k * 64);
#pragma unroll
            for (int j4 = 0; j4 < 8; j4++) {
                float4 w = w4[j4];
                o[j4 * 4 + 0] += h * w.x;
                o[j4 * 4 + 1] += h * w.y;
                o[j4 * 4 + 2] += h * w.z;
                o[j4 * 4 + 3] += h * w.w;
            }
        }
#pragma unroll
        for (int k = 0; k < 16; k++) {
            float h = hhi[k];
            const float4* w4 = (const float4*)(w3b + (k + 16) * 64);
#pragma unroll
            for (int j4 = 0; j4 < 8; j4++) {
                float4 w = w4[j4];
                o[j4 * 4 + 0] += h * w.x;
                o[j4 * 4 + 1] += h * w.y;
                o[j4 * 4 + 2] += h * w.z;
                o[j4 * 4 + 3] += h * w.w;
            }
        }

        float s1 = 0.f;
#pragma unroll
        for (int j = 0; j < 32; j++) s1 += o[j];
        s1 += __shfl_xor_sync(FULL, s1, 1);
        float mu = s1 * (1.f / 64.f);
        float s2 = 0.f;
#pragma unroll
        for (int j = 0; j < 32; j++) { float d = o[j] - mu; s2 += d * d; }
        s2 += __shfl_xor_sync(FULL, s2, 1);
        float x = s2 * (1.f / 64.f) + LN_EPS;
        float rinv = rsqrtf(x);
        rinv = rinv * (1.5f - 0.5f * x * rinv * rinv);

        const float wg = wgate2[s];
        const float* gm = sm + T5_GM + s * 64 + half * 32;
        const float* bt = sm + T5_BT + s * 64 + half * 32;
        if (s == 0) {
#pragma unroll
            for (int j = 0; j < 32; j++)
                z[j] = wg * (gm[j] * (o[j] - mu) * rinv + bt[j]);
        } else {
#pragma unroll
            for (int j = 0; j < 32; j++)
                z[j] += wg * (gm[j] * (o[j] - mu) * rinv + bt[j]);
        }
    }

    float* obase = out + ((size_t)p * B_TOK + tok) * D_OUT + half * 32;
#pragma unroll
    for (int j4 = 0; j4 < 8; j4++) {
        float4 y;
        y.x = z[j4 * 4 + 0]; y.y = z[j4 * 4 + 1];
        y.z = z[j4 * 4 + 2]; y.w = z[j4 * 4 + 3];
        *(float4*)(obase + j4 * 4) = y;
    }
}

// ---------------------------------------------------------------------------
// Launch
// ---------------------------------------------------------------------------
extern "C" void kernel_launch(void* const* d_in, const int* in_sizes, int n_in,
                              void* d_out, int out_size) {
    (void)in_sizes; (void)n_in; (void)out_size;
    const float* v    = (const float*)d_in[0];
    const float* sw1  = (const float*)d_in[1];
    const float* sb1  = (const float*)d_in[2];
    const float* sw2  = (const float*)d_in[3];
    const float* sb2  = (const float*)d_in[4];
    const float* sw3  = (const float*)d_in[5];
    const float* sb3  = (const float*)d_in[6];
    const float* sgam = (const float*)d_in[7];
    const float* sbet = (const float*)d_in[8];
    const float* sgw1 = (const float*)d_in[9];
    const float* sgb1 = (const float*)d_in[10];
    const float* sgw2 = (const float*)d_in[11];
    const float* sgb2 = (const float*)d_in[12];
    const float* gw1  = (const float*)d_in[13];
    const float* gb1  = (const float*)d_in[14];
    const float* gw2  = (const float*)d_in[15];
    const float* gb2  = (const float*)d_in[16];
    const float* gw3  = (const float*)d_in[17];
    const float* gb3  = (const float*)d_in[18];
    const float* ggam = (const float*)d_in[19];
    const float* gbet = (const float*)d_in[20];
    const float* ggw1 = (const float*)d_in[21];
    const float* ggb1 = (const float*)d_in[22];
    const float* ggw2 = (const float*)d_in[23];
    const float* ggb2 = (const float*)d_in[24];
    float* out = (float*)d_out;

    prep_kernel<<<CONV_BLOCKS + (NCATP * D_IN) / 256, 256>>>(
        v, sw1, sb1, gw1, gb1, sgw1, sgb1, ggw1, ggb1);

    cudaFuncSetAttribute(gemm1_mma_kernel, cudaFuncAttributeMaxDynamicSharedMemorySize, GEMM_SMEM);
    dim3 g1(NCATP / 128, B_TOK / 128);
    gemm1_mma_kernel<<<g1, 256, GEMM_SMEM>>>();

    cudaFuncSetAttribute(tail5_kernel, cudaFuncAttributeMaxDynamicSharedMemorySize, T5_SMEM);
    dim3 g2(B_TOK / 128, 3);
    tail5_kernel<<<g2, 256, T5_SMEM>>>(sw2, sb2, sw3, sb3, sgam, sbet, sgw2, sgb2,
                                       gw2, gb2, gw3, gb3, ggam, gbet, ggw2, ggb2, out);
}

// round 12
// speedup vs baseline: 1.5983x; 1.1622x over previous
#include <cuda_runtime.h>
#include <cuda_fp16.h>
#include <math.h>
#include <stddef.h>
#include <stdint.h>

// ---------------------------------------------------------------------------
// Problem constants
// ---------------------------------------------------------------------------
#define B_TOK   16384
#define D_IN    512
#define D_OUT   64
#define H1      64
#define H2      32
#define GH      32
#define NEXP    6
#define NCAT    480
#define NCATP   512
#define LN_EPS  1e-5f

// ---------------------------------------------------------------------------
// Device scratch
// ---------------------------------------------------------------------------
__device__ __align__(16) __half g_vh[(size_t)B_TOK * D_IN];    // fp16(v)
__device__ __align__(16) __half g_wh[NCATP * D_IN];            // [n][k] fp16 hi
__device__ __align__(16) __half g_wl[NCATP * D_IN];            // [n][k] fp16 lo
__device__ float g_bc[NCATP];
__device__ __align__(16) float g_HT[(size_t)NCATP * B_TOK];    // H transposed [col][token]

__device__ __forceinline__ uint32_t smem_u32(const void* p) {
    uint32_t a;
    asm("{ .reg .u64 t; cvta.to.shared.u64 t, %1; cvt.u32.u64 %0, t; }" : "=r"(a) : "l"(p));
    return a;
}

// ---------------------------------------------------------------------------
// Kernel: prep = conv_v (blocks 0..8191) + pack_w (blocks 8192..9215)
// ---------------------------------------------------------------------------
#define CONV_BLOCKS 8192
__global__ __launch_bounds__(256) void prep_kernel(
    const float* __restrict__ v,
    const float* __restrict__ sw1, const float* __restrict__ sb1,
    const float* __restrict__ gw1, const float* __restrict__ gb1,
    const float* __restrict__ sgw1, const float* __restrict__ sgb1,
    const float* __restrict__ ggw1, const float* __restrict__ ggb1) {
    if (blockIdx.x < CONV_BLOCKS) {
        size_t i = ((size_t)blockIdx.x * 256 + threadIdx.x) * 4;
        float4 x = *(const float4*)(v + i);
        __half2* ph = (__half2*)(g_vh + i);
        ph[0] = __floats2half2_rn(x.x, x.y);
        ph[1] = __floats2half2_rn(x.z, x.w);
    } else {
        int idx = (blockIdx.x - CONV_BLOCKS) * 256 + threadIdx.x;   // over 512*512
        int n = idx >> 9, k = idx & 511;
        float w = 0.f;
        if (n < 384) {
            int e = n >> 6, j = n & 63;
            w = (e < 2) ? sw1[((size_t)e * D_IN + k) * 64 + j]
                        : gw1[((size_t)(e - 2) * D_IN + k) * 64 + j];
        } else if (n < 480) {
            int m = n - 384, s = m >> 5, j = m & 31;
            w = (s == 0) ? sgw1[k * 32 + j]
                         : ggw1[((size_t)(s - 1) * D_IN + k) * 32 + j];
        }
        __half hi = __float2half_rn(w);
        g_wh[idx] = hi;
        g_wl[idx] = __float2half_rn(w - __half2float(hi));
        if (idx < NCATP) {
            float b = 0.f;
            if (idx < 384) {
                int e = idx >> 6, j = idx & 63;
                b = (e < 2) ? sb1[e * 64 + j] : gb1[(e - 2) * 64 + j];
            } else if (idx < 480) {
                int m = idx - 384, s = m >> 5, j = m & 31;
                b = (s == 0) ? sgb1[j] : ggb1[(s - 1) * GH + j];
            }
            g_bc[idx] = b;
        }
    }
}

// ---------------------------------------------------------------------------
// Kernel: H^T = silu(v @ W + b)^T via mma.sync fp16 2-pass split
// (Ah*Bh + Ah*Bl; dropped Al*Bh term ~1.6e-4 rel err).
// 3-stage cp.async pipeline (prefetch distance 2), K chunks of 32,
// ONE __syncthreads per chunk. CTA 128x128, warps 2(M)x4(N).
// SMEM rows: 64B natural stride + XOR swizzle seg' = seg ^ ((row>>1)&3).
// ---------------------------------------------------------------------------
#define KCH2    32
#define OPB     (128 * 64)                  // 8192 per operand per stage
#define STAGE_B (3 * OPB)                   // 24576 (A, Bh, Bl)
#define NSTAGE  3
#define SMO_BIAS (NSTAGE * STAGE_B)         // 73728
#define GEMM_SMEM (SMO_BIAS + 512)          // 74240
#define STG_STRIDE 136                      // floats, epilogue stage [col][row]
#define NCHUNK  (D_IN / KCH2)               // 16

#define CPASYNC16(dst, src) \
    asm volatile("cp.async.cg.shared.global [%0], [%1], 16;" :: "r"(dst), "l"(src))

__device__ __forceinline__ void ldsm_x4(uint32_t* r, uint32_t a) {
    asm volatile("ldmatrix.sync.aligned.m8n8.x4.shared.b16 {%0,%1,%2,%3}, [%4];"
                 : "=r"(r[0]), "=r"(r[1]), "=r"(r[2]), "=r"(r[3]) : "r"(a));
}
__device__ __forceinline__ void mma_f16(float* c, const uint32_t* a, uint32_t b0, uint32_t b1) {
    asm volatile(
        "mma.sync.aligned.m16n8k16.row.col.f32.f16.f16.f32 "
        "{%0,%1,%2,%3}, {%4,%5,%6,%7}, {%8,%9}, {%0,%1,%2,%3};"
        : "+f"(c[0]), "+f"(c[1]), "+f"(c[2]), "+f"(c[3])
        : "r"(a[0]), "r"(a[1]), "r"(a[2]), "r"(a[3]), "r"(b0), "r"(b1));
}

__global__ void __launch_bounds__(256, 2) gemm1_mma_kernel() {
    extern __shared__ char smem[];
    const uint32_t sb = smem_u32(smem);
    const int tid  = threadIdx.x;
    const int lane = tid & 31;
    const int warp = tid >> 5;
    const int wm = warp >> 2;
    const int wn = warp & 3;
    const int bm = blockIdx.y * 128;
    const int bn = blockIdx.x * 128;

    if (tid < 128) ((float*)(smem + SMO_BIAS))[tid] = g_bc[bn + tid];

    // cp.async geometry: per operand 128 rows x 4 segs of 16B; 2 (row,seg)
    // pairs per thread. seg' = seg ^ ((row>>1)&3).
    const int r0 = tid >> 2, r1 = r0 + 64;
    const int seg = tid & 3;
    const uint32_t d0 = (uint32_t)(r0 * 64 + ((seg ^ ((r0 >> 1) & 3)) << 4));
    const uint32_t d1 = (uint32_t)(r1 * 64 + ((seg ^ ((r1 >> 1) & 3)) << 4));
    const int selem = seg * 8;              // fp16 elements into the 64B k-chunk

    // ldmatrix lane geometry
    const int mi = lane >> 3;
    const int a_row = (lane & 7) + ((mi & 1) << 3);
    const int akb4  = (mi >= 2) ? 1 : 0;
    const int b_row = (lane & 7) + ((mi >= 2) ? 8 : 0);
    const int bkb4  = (mi & 1) ? 1 : 0;
    const int arsw  = (a_row >> 1) & 3;
    const int brsw  = (b_row >> 1) & 3;

    float acc[4][4][4];
#pragma unroll
    for (int i = 0; i < 4; i++)
#pragma unroll
        for (int j = 0; j < 4; j++)
#pragma unroll
            for (int u = 0; u < 4; u++) acc[i][j][u] = 0.f;

    auto load_chunk = [&](int ch, int stg) {
        const int k0 = ch * KCH2;
        const uint32_t base = sb + stg * STAGE_B;
        const __half* sa0 = g_vh + (size_t)(bm + r0) * D_IN + k0 + selem;
        const __half* sa1 = g_vh + (size_t)(bm + r1) * D_IN + k0 + selem;
        const __half* sh0 = g_wh + (size_t)(bn + r0) * D_IN + k0 + selem;
        const __half* sh1 = g_wh + (size_t)(bn + r1) * D_IN + k0 + selem;
        const ptrdiff_t dwl = g_wl - g_wh;
        CPASYNC16(base + 0 * OPB + d0, sa0);
        CPASYNC16(base + 0 * OPB + d1, sa1);
        CPASYNC16(base + 1 * OPB + d0, sh0);
        CPASYNC16(base + 1 * OPB + d1, sh1);
        CPASYNC16(base + 2 * OPB + d0, sh0 + dwl);
        CPASYNC16(base + 2 * OPB + d1, sh1 + dwl);
    };

    // prologue: prefetch chunks 0 and 1
    load_chunk(0, 0);
    asm volatile("cp.async.commit_group;");
    load_chunk(1, 1);
    asm volatile("cp.async.commit_group;");

    for (int ch = 0; ch < NCHUNK; ch++) {
        if (ch < NCHUNK - 1) {
            asm volatile("cp.async.wait_group 1;");
        } else {
            asm volatile("cp.async.wait_group 0;");
        }
        __syncthreads();   // single barrier per chunk

        // prefetch chunk ch+2 into stage (ch+2)%3 — computed at ch-1, and the
        // barrier above guarantees all threads are past that compute.
        if (ch + 2 < NCHUNK) {
            load_chunk(ch + 2, (ch + 2) % NSTAGE);
            asm volatile("cp.async.commit_group;");
        }

        const uint32_t stgb  = sb + (ch % NSTAGE) * STAGE_B;
        const uint32_t aBase = stgb + 0 * OPB + (uint32_t)((wm * 64 + a_row) * 64);
        const uint32_t bBase = stgb + 1 * OPB + (uint32_t)((wn * 32 + b_row) * 64);

#pragma unroll
        for (int kt = 0; kt < 2; kt++) {
            const uint32_t aoff = (uint32_t)(((kt * 2 + akb4) ^ arsw) << 4);
            const uint32_t boff = (uint32_t)(((kt * 2 + bkb4) ^ brsw) << 4);
            uint32_t ah[4][4], bh[2][4], bl[2][4];
#pragma unroll
            for (int mt = 0; mt < 4; mt++)
                ldsm_x4(ah[mt], aBase + mt * 1024 + aoff);
#pragma unroll
            for (int h = 0; h < 2; h++)
                ldsm_x4(bh[h], bBase + h * 1024 + boff);
#pragma unroll
            for (int mt = 0; mt < 4; mt++)
#pragma unroll
                for (int nt = 0; nt < 4; nt++)
                    mma_f16(acc[mt][nt], ah[mt], bh[nt >> 1][(nt & 1) * 2], bh[nt >> 1][(nt & 1) * 2 + 1]);
#pragma unroll
            for (int h = 0; h < 2; h++)
                ldsm_x4(bl[h], bBase + OPB + h * 1024 + boff);
#pragma unroll
            for (int mt = 0; mt < 4; mt++)
#pragma unroll
                for (int nt = 0; nt < 4; nt++)
                    mma_f16(acc[mt][nt], ah[mt], bl[nt >> 1][(nt & 1) * 2], bl[nt >> 1][(nt & 1) * 2 + 1]);
        }
    }
    __syncthreads();

    // Epilogue: bias + silu -> smem stage [col][row] -> coalesced g_HT writes
    {
        float* stg = (float*)smem;
        const float* bias = (const float*)(smem + SMO_BIAS);
#pragma unroll
        for (int mt = 0; mt < 4; mt++) {
#pragma unroll
            for (int nt = 0; nt < 4; nt++) {
#pragma unroll
                for (int u = 0; u < 4; u++) {
                    int row = wm * 64 + mt * 16 + (lane >> 2) + ((u >> 1) << 3);
                    int col = wn * 32 + nt * 8 + 2 * (lane & 3) + (u & 1);
                    float x = acc[mt][nt][u] + bias[col];
                    stg[col * STG_STRIDE + row] = x / (1.f + __expf(-x));
                }
            }
        }
        __syncthreads();
#pragma unroll
        for (int cl = 0; cl < 16; cl++) {
            int col = warp * 16 + cl;
            int gc = bn + col;
            if (gc < NCAT) {
                float4 val = *(float4*)&stg[col * STG_STRIDE + lane * 4];
                *(float4*)(g_HT + (size_t)gc * B_TOK + bm + lane * 4) = val;
            }
        }
    }
}

// ---------------------------------------------------------------------------
// Kernel: tail5 — slot-per-CTA, 256 threads, 128 tokens, 2 threads/token.
// (verbatim — best known tail at 62.4us)
// ---------------------------------------------------------------------------
#define T5_H1   0                         // 2*64*128 = 16384
#define T5_W2   16384                     // 2*2048
#define T5_W3   20480                     // 2*2048
#define T5_B2   24576                     // 2*32
#define T5_B3   24640                     // 2*64
#define T5_GM   24768                     // 2*64
#define T5_BT   24896                     // 2*64
#define T5_GW   25024                     // 64
#define T5_GB   25088                     // 2
#define T5_FLOATS 25090
#define T5_SMEM (T5_FLOATS * 4)

__global__ void __launch_bounds__(256, 2) tail5_kernel(
    const float* __restrict__ sw2, const float* __restrict__ sb2,
    const float* __restrict__ sw3, const float* __restrict__ sb3,
    const float* __restrict__ sgam, const float* __restrict__ sbet,
    const float* __restrict__ sgw2, const float* __restrict__ sgb2,
    const float* __restrict__ gw2, const float* __restrict__ gb2,
    const float* __restrict__ gw3, const float* __restrict__ gb3,
    const float* __restrict__ ggam, const float* __restrict__ gbet,
    const float* __restrict__ ggw2, const float* __restrict__ ggb2,
    float* __restrict__ out) {
    extern __shared__ float sm[];
    const unsigned FULL = 0xffffffffu;

    const int p    = blockIdx.y;          // 0=group0(e2,3) 1=group1(e4,5) 2=shared(e0,1)
    const int tid  = threadIdx.x;
    const int half = tid & 1;
    const int ltok = tid >> 1;            // 0..127
    const int t0   = blockIdx.x * 128;
    const int tok  = t0 + ltok;
    const int e_base = (p == 2) ? 0 : ((p == 0) ? 2 : 4);
    const int gslot  = (p == 2) ? 0 : (p + 1);

    {
        const float* src = g_HT + (size_t)(e_base * 64) * B_TOK + t0;
#pragma unroll
        for (int k = 0; k < 16; k++) {
            int lin = tid + k * 256;          // 0..4095
            int row = lin >> 5, q = lin & 31;
            float4 val = *(const float4*)(src + (size_t)row * B_TOK + q * 4);
            *(float4*)&sm[T5_H1 + row * 128 + q * 4] = val;
        }
    }
#pragma unroll
    for (int s = 0; s < 2; s++) {
        const int e = e_base + s;
        const float* w2src = (e < 2) ? (sw2 + (size_t)e * 2048) : (gw2 + (size_t)(e - 2) * 2048);
        const float* w3src = (e < 2) ? (sw3 + (size_t)e * 2048) : (gw3 + (size_t)(e - 2) * 2048);
        for (int i = tid; i < 2048; i += 256) {
            sm[T5_W2 + s * 2048 + i] = w2src[i];
            sm[T5_W3 + s * 2048 + i] = w3src[i];
        }
        if (tid < H2) sm[T5_B2 + s * 32 + tid] = (e < 2) ? sb2[e * 32 + tid] : gb2[(e - 2) * 32 + tid];
        if (tid < D_OUT) {
            sm[T5_B3 + s * 64 + tid] = (e < 2) ? sb3[e * 64 + tid]  : gb3[(e - 2) * 64 + tid];
            sm[T5_GM + s * 64 + tid] = (e < 2) ? sgam[e * 64 + tid] : ggam[(e - 2) * 64 + tid];
            sm[T5_BT + s * 64 + tid] = (e < 2) ? sbet[e * 64 + tid] : gbet[(e - 2) * 64 + tid];
        }
    }
    if (tid < 64) sm[T5_GW + tid] = (gslot == 0) ? sgw2[tid] : ggw2[(gslot - 1) * 64 + tid];
    if (tid < 2)  sm[T5_GB + tid] = (gslot == 0) ? sgb2[tid] : ggb2[(gslot - 1) * 2 + tid];
    __syncthreads();

    float wgate2[2];
    {
        float l0 = sm[T5_GB + 0], l1 = sm[T5_GB + 1];
        const float* gbase = g_HT + (size_t)(384 + gslot * 32) * B_TOK + tok;
#pragma unroll 8
        for (int i = 0; i < GH; i++) {
            float hg = gbase[(size_t)i * B_TOK];
            l0 += hg * sm[T5_GW + i * 2];
            l1 += hg * sm[T5_GW + i * 2 + 1];
        }
        float mx = fmaxf(l0, l1);
        float ea = __expf(l0 - mx), eb = __expf(l1 - mx);
        float inv_s = 1.f / (ea + eb);
        wgate2[0] = ea * inv_s;
        wgate2[1] = eb * inv_s;
    }

    float z[32];

#pragma unroll
    for (int s = 0; s < 2; s++) {
        const float* h1b = sm + T5_H1 + s * 8192;
        const float* w2b = sm + T5_W2 + s * 2048 + half * 16;

        float h2[16];
        {
            const float* b2 = sm + T5_B2 + s * 32 + half * 16;
#pragma unroll
            for (int j = 0; j < 16; j++) h2[j] = b2[j];
        }
#pragma unroll 8
        for (int i = 0; i < H1; i++) {
            float a = h1b[i * 128 + ltok];
            const float4* w4 = (const float4*)(w2b + i * 32);
#pragma unroll
            for (int j4 = 0; j4 < 4; j4++) {
                float4 w = w4[j4];
                h2[j4 * 4 + 0] += a * w.x;
                h2[j4 * 4 + 1] += a * w.y;
                h2[j4 * 4 + 2] += a * w.z;
                h2[j4 * 4 + 3] += a * w.w;
            }
        }
#pragma unroll
        for (int j = 0; j < 16; j++) h2[j] = h2[j] / (1.f + __expf(-h2[j]));

        float hlo[16], hhi[16];
#pragma unroll
        for (int j = 0; j < 16; j++) {
            float other = __shfl_xor_sync(FULL, h2[j], 1);
            hlo[j] = half ? other : h2[j];
            hhi[j] = half ? h2[j] : other;
        }

        float o[32];
        {
            const float* b3 = sm + T5_B3 + s * 64 + half * 32;
#pragma unroll
            for (int j = 0; j < 32; j++) o[j] = b3[j];
        }
        const float* w3b = sm + T5_W3 + s * 2048 + half * 32;
#pragma unroll
        for (int k = 0; k < 16; k++) {
            float h = hlo[k];
            const float4* w4 = (const float4*)(w3b + k * 64);
#pragma unroll
            for (int j4 = 0; j4 < 8; j4++) {
                float4 w = w4[j4];
                o[j4 * 4 + 0] += h * w.x;
                o[j4 * 4 + 1] += h * w.y;
                o[j4 * 4 + 2] += h * w.z;
                o[j4 * 4 + 3] += h * w.w;
            }
        }
#pragma unroll
        for (int k = 0; k < 16; k++) {
            float h = hhi[k];
            const float4* w4 = (const float4*)(w3b + (k + 16) * 64);
#pragma unroll
            for (int j4 = 0; j4 < 8; j4++) {
                float4 w = w4[j4];
                o[j4 * 4 + 0] += h * w.x;
                o[j4 * 4 + 1] += h * w.y;
                o[j4 * 4 + 2] += h * w.z;
                o[j4 * 4 + 3] += h * w.w;
            }
        }

        float s1 = 0.f;
#pragma unroll
        for (int j = 0; j < 32; j++) s1 += o[j];
        s1 += __shfl_xor_sync(FULL, s1, 1);
        float mu = s1 * (1.f / 64.f);
        float s2 = 0.f;
#pragma unroll
        for (int j = 0; j < 32; j++) { float d = o[j] - mu; s2 += d * d; }
        s2 += __shfl_xor_sync(FULL, s2, 1);
        float x = s2 * (1.f / 64.f) + LN_EPS;
        float rinv = rsqrtf(x);
        rinv = rinv * (1.5f - 0.5f * x * rinv * rinv);

        const float wg = wgate2[s];
        const float* gm = sm + T5_GM + s * 64 + half * 32;
        const float* bt = sm + T5_BT + s * 64 + half * 32;
        if (s == 0) {
#pragma unroll
            for (int j = 0; j < 32; j++)
                z[j] = wg * (gm[j] * (o[j] - mu) * rinv + bt[j]);
        } else {
#pragma unroll
            for (int j = 0; j < 32; j++)
                z[j] += wg * (gm[j] * (o[j] - mu) * rinv + bt[j]);
        }
    }

    float* obase = out + ((size_t)p * B_TOK + tok) * D_OUT + half * 32;
#pragma unroll
    for (int j4 = 0; j4 < 8; j4++) {
        float4 y;
        y.x = z[j4 * 4 + 0]; y.y = z[j4 * 4 + 1];
        y.z = z[j4 * 4 + 2]; y.w = z[j4 * 4 + 3];
        *(float4*)(obase + j4 * 4) = y;
    }
}

// ---------------------------------------------------------------------------
// Launch
// ---------------------------------------------------------------------------
extern "C" void kernel_launch(void* const* d_in, const int* in_sizes, int n_in,
                              void* d_out, int out_size) {
    (void)in_sizes; (void)n_in; (void)out_size;
    const float* v    = (const float*)d_in[0];
    const float* sw1  = (const float*)d_in[1];
    const float* sb1  = (const float*)d_in[2];
    const float* sw2  = (const float*)d_in[3];
    const float* sb2  = (const float*)d_in[4];
    const float* sw3  = (const float*)d_in[5];
    const float* sb3  = (const float*)d_in[6];
    const float* sgam = (const float*)d_in[7];
    const float* sbet = (const float*)d_in[8];
    const float* sgw1 = (const float*)d_in[9];
    const float* sgb1 = (const float*)d_in[10];
    const float* sgw2 = (const float*)d_in[11];
    const float* sgb2 = (const float*)d_in[12];
    const float* gw1  = (const float*)d_in[13];
    const float* gb1  = (const float*)d_in[14];
    const float* gw2  = (const float*)d_in[15];
    const float* gb2  = (const float*)d_in[16];
    const float* gw3  = (const float*)d_in[17];
    const float* gb3  = (const float*)d_in[18];
    const float* ggam = (const float*)d_in[19];
    const float* gbet = (const float*)d_in[20];
    const float* ggw1 = (const float*)d_in[21];
    const float* ggb1 = (const float*)d_in[22];
    const float* ggw2 = (const float*)d_in[23];
    const float* ggb2 = (const float*)d_in[24];
    float* out = (float*)d_out;

    prep_kernel<<<CONV_BLOCKS + (NCATP * D_IN) / 256, 256>>>(
        v, sw1, sb1, gw1, gb1, sgw1, sgb1, ggw1, ggb1);

    cudaFuncSetAttribute(gemm1_mma_kernel, cudaFuncAttributeMaxDynamicSharedMemorySize, GEMM_SMEM);
    dim3 g1(NCATP / 128, B_TOK / 128);
    gemm1_mma_kernel<<<g1, 256, GEMM_SMEM>>>();

    cudaFuncSetAttribute(tail5_kernel, cudaFuncAttributeMaxDynamicSharedMemorySize, T5_SMEM);
    dim3 g2(B_TOK / 128, 3);
    tail5_kernel<<<g2, 256, T5_SMEM>>>(sw2, sb2, sw3, sb3, sgam, sbet, sgw2, sgb2,
                                       gw2, gb2, gw3, gb3, ggam, gbet, ggw2, ggb2, out);
}

// round 14
// speedup vs baseline: 1.9354x; 1.2109x over previous
#include <cuda_runtime.h>
#include <cuda_fp16.h>
#include <math.h>
#include <stddef.h>
#include <stdint.h>

// ---------------------------------------------------------------------------
// Problem constants
// ---------------------------------------------------------------------------
#define B_TOK   16384
#define D_IN    512
#define D_OUT   64
#define H1      64
#define H2      32
#define GH      32
#define NEXP    6
#define NCAT    480
#define NCATP   512
#define LN_EPS  1e-5f

// ---------------------------------------------------------------------------
// Device scratch
// ---------------------------------------------------------------------------
__device__ __align__(16) __half g_vh[(size_t)B_TOK * D_IN];    // fp16(v)
__device__ __align__(16) __half g_wh[NCATP * D_IN];            // [n][k] fp16
__device__ float g_bc[NCATP];
__device__ __align__(16) float g_HT[(size_t)NCATP * B_TOK];    // H transposed [col][token]

__device__ __forceinline__ uint32_t smem_u32(const void* p) {
    uint32_t a;
    asm("{ .reg .u64 t; cvta.to.shared.u64 t, %1; cvt.u32.u64 %0, t; }" : "=r"(a) : "l"(p));
    return a;
}

// ---------------------------------------------------------------------------
// Kernel: prep = conv_v (blocks 0..8191) + pack_w (blocks 8192..9215)
// ---------------------------------------------------------------------------
#define CONV_BLOCKS 8192
__global__ __launch_bounds__(256) void prep_kernel(
    const float* __restrict__ v,
    const float* __restrict__ sw1, const float* __restrict__ sb1,
    const float* __restrict__ gw1, const float* __restrict__ gb1,
    const float* __restrict__ sgw1, const float* __restrict__ sgb1,
    const float* __restrict__ ggw1, const float* __restrict__ ggb1) {
    if (blockIdx.x < CONV_BLOCKS) {
        size_t i = ((size_t)blockIdx.x * 256 + threadIdx.x) * 4;
        float4 x = *(const float4*)(v + i);
        __half2* ph = (__half2*)(g_vh + i);
        ph[0] = __floats2half2_rn(x.x, x.y);
        ph[1] = __floats2half2_rn(x.z, x.w);
    } else {
        int idx = (blockIdx.x - CONV_BLOCKS) * 256 + threadIdx.x;   // over 512*512
        int n = idx >> 9, k = idx & 511;
        float w = 0.f;
        if (n < 384) {
            int e = n >> 6, j = n & 63;
            w = (e < 2) ? sw1[((size_t)e * D_IN + k) * 64 + j]
                        : gw1[((size_t)(e - 2) * D_IN + k) * 64 + j];
        } else if (n < 480) {
            int m = n - 384, s = m >> 5, j = m & 31;
            w = (s == 0) ? sgw1[k * 32 + j]
                         : ggw1[((size_t)(s - 1) * D_IN + k) * 32 + j];
        }
        g_wh[idx] = __float2half_rn(w);
        if (idx < NCATP) {
            float b = 0.f;
            if (idx < 384) {
                int e = idx >> 6, j = idx & 63;
                b = (e < 2) ? sb1[e * 64 + j] : gb1[(e - 2) * 64 + j];
            } else if (idx < 480) {
                int m = idx - 384, s = m >> 5, j = m & 31;
                b = (s == 0) ? sgb1[j] : ggb1[(s - 1) * GH + j];
            }
            g_bc[idx] = b;
        }
    }
}

// ---------------------------------------------------------------------------
// Kernel: H^T = silu(v @ W + b)^T via SINGLE-PASS fp16 mma.sync
// (error = input quantization only, ~3e-4 rel; HMMA products exact in fp32).
// 3-stage cp.async pipeline (prefetch distance 2), K chunks of 32,
// ONE __syncthreads per chunk. CTA 128x128, warps 2(M)x4(N).
// SMEM rows: 64B natural stride + XOR swizzle seg' = seg ^ ((row>>1)&3).
// SMEM allocation must cover the EPILOGUE STAGING region (128*136*4 = 69632B),
// which exceeds the 3-stage pipeline footprint (49152B) — bias lives above it.
// ---------------------------------------------------------------------------
#define KCH2    32
#define OPB     (128 * 64)                  // 8192 per operand per stage
#define STAGE_B (2 * OPB)                   // 16384 (A, B)
#define NSTAGE  3
#define STG_STRIDE 136                      // floats, epilogue stage [col][row]
#define STG_BYTES  (128 * STG_STRIDE * 4)   // 69632
#define SMO_BIAS   STG_BYTES                // 69632 (> 3*STAGE_B = 49152)
#define GEMM_SMEM  (SMO_BIAS + 512)         // 70144
#define NCHUNK  (D_IN / KCH2)               // 16

#define CPASYNC16(dst, src) \
    asm volatile("cp.async.cg.shared.global [%0], [%1], 16;" :: "r"(dst), "l"(src))

__device__ __forceinline__ void ldsm_x4(uint32_t* r, uint32_t a) {
    asm volatile("ldmatrix.sync.aligned.m8n8.x4.shared.b16 {%0,%1,%2,%3}, [%4];"
                 : "=r"(r[0]), "=r"(r[1]), "=r"(r[2]), "=r"(r[3]) : "r"(a));
}
__device__ __forceinline__ void mma_f16(float* c, const uint32_t* a, uint32_t b0, uint32_t b1) {
    asm volatile(
        "mma.sync.aligned.m16n8k16.row.col.f32.f16.f16.f32 "
        "{%0,%1,%2,%3}, {%4,%5,%6,%7}, {%8,%9}, {%0,%1,%2,%3};"
        : "+f"(c[0]), "+f"(c[1]), "+f"(c[2]), "+f"(c[3])
        : "r"(a[0]), "r"(a[1]), "r"(a[2]), "r"(a[3]), "r"(b0), "r"(b1));
}

__global__ void __launch_bounds__(256, 2) gemm1_mma_kernel() {
    extern __shared__ char smem[];
    const uint32_t sb = smem_u32(smem);
    const int tid  = threadIdx.x;
    const int lane = tid & 31;
    const int warp = tid >> 5;
    const int wm = warp >> 2;
    const int wn = warp & 3;
    const int bm = blockIdx.y * 128;
    const int bn = blockIdx.x * 128;

    if (tid < 128) ((float*)(smem + SMO_BIAS))[tid] = g_bc[bn + tid];

    // cp.async geometry: per operand 128 rows x 4 segs of 16B; 2 (row,seg)
    // pairs per thread. seg' = seg ^ ((row>>1)&3).
    const int r0 = tid >> 2, r1 = r0 + 64;
    const int seg = tid & 3;
    const uint32_t d0 = (uint32_t)(r0 * 64 + ((seg ^ ((r0 >> 1) & 3)) << 4));
    const uint32_t d1 = (uint32_t)(r1 * 64 + ((seg ^ ((r1 >> 1) & 3)) << 4));
    const int selem = seg * 8;              // fp16 elements into the 64B k-chunk

    // ldmatrix lane geometry
    const int mi = lane >> 3;
    const int a_row = (lane & 7) + ((mi & 1) << 3);
    const int akb4  = (mi >= 2) ? 1 : 0;
    const int b_row = (lane & 7) + ((mi >= 2) ? 8 : 0);
    const int bkb4  = (mi & 1) ? 1 : 0;
    const int arsw  = (a_row >> 1) & 3;
    const int brsw  = (b_row >> 1) & 3;

    float acc[4][4][4];
#pragma unroll
    for (int i = 0; i < 4; i++)
#pragma unroll
        for (int j = 0; j < 4; j++)
#pragma unroll
            for (int u = 0; u < 4; u++) acc[i][j][u] = 0.f;

    auto load_chunk = [&](int ch, int stg) {
        const int k0 = ch * KCH2;
        const uint32_t base = sb + stg * STAGE_B;
        const __half* sa0 = g_vh + (size_t)(bm + r0) * D_IN + k0 + selem;
        const __half* sa1 = g_vh + (size_t)(bm + r1) * D_IN + k0 + selem;
        const __half* sh0 = g_wh + (size_t)(bn + r0) * D_IN + k0 + selem;
        const __half* sh1 = g_wh + (size_t)(bn + r1) * D_IN + k0 + selem;
        CPASYNC16(base + 0 * OPB + d0, sa0);
        CPASYNC16(base + 0 * OPB + d1, sa1);
        CPASYNC16(base + 1 * OPB + d0, sh0);
        CPASYNC16(base + 1 * OPB + d1, sh1);
    };

    // prologue: prefetch chunks 0 and 1
    load_chunk(0, 0);
    asm volatile("cp.async.commit_group;");
    load_chunk(1, 1);
    asm volatile("cp.async.commit_group;");

    for (int ch = 0; ch < NCHUNK; ch++) {
        if (ch < NCHUNK - 1) {
            asm volatile("cp.async.wait_group 1;");
        } else {
            asm volatile("cp.async.wait_group 0;");
        }
        __syncthreads();   // single barrier per chunk

        // prefetch chunk ch+2 into stage (ch+2)%3 — computed at ch-1, and the
        // barrier above guarantees all threads are past that compute.
        if (ch + 2 < NCHUNK) {
            load_chunk(ch + 2, (ch + 2) % NSTAGE);
            asm volatile("cp.async.commit_group;");
        }

        const uint32_t stgb  = sb + (ch % NSTAGE) * STAGE_B;
        const uint32_t aBase = stgb + 0 * OPB + (uint32_t)((wm * 64 + a_row) * 64);
        const uint32_t bBase = stgb + 1 * OPB + (uint32_t)((wn * 32 + b_row) * 64);

#pragma unroll
        for (int kt = 0; kt < 2; kt++) {
            const uint32_t aoff = (uint32_t)(((kt * 2 + akb4) ^ arsw) << 4);
            const uint32_t boff = (uint32_t)(((kt * 2 + bkb4) ^ brsw) << 4);
            uint32_t ah[4][4], bh[2][4];
#pragma unroll
            for (int mt = 0; mt < 4; mt++)
                ldsm_x4(ah[mt], aBase + mt * 1024 + aoff);
#pragma unroll
            for (int h = 0; h < 2; h++)
                ldsm_x4(bh[h], bBase + h * 1024 + boff);
#pragma unroll
            for (int mt = 0; mt < 4; mt++)
#pragma unroll
                for (int nt = 0; nt < 4; nt++)
                    mma_f16(acc[mt][nt], ah[mt], bh[nt >> 1][(nt & 1) * 2], bh[nt >> 1][(nt & 1) * 2 + 1]);
        }
    }
    __syncthreads();

    // Epilogue: bias + silu -> smem stage [col][row] -> coalesced g_HT writes
    {
        float* stg = (float*)smem;
        const float* bias = (const float*)(smem + SMO_BIAS);
#pragma unroll
        for (int mt = 0; mt < 4; mt++) {
#pragma unroll
            for (int nt = 0; nt < 4; nt++) {
#pragma unroll
                for (int u = 0; u < 4; u++) {
                    int row = wm * 64 + mt * 16 + (lane >> 2) + ((u >> 1) << 3);
                    int col = wn * 32 + nt * 8 + 2 * (lane & 3) + (u & 1);
                    float x = acc[mt][nt][u] + bias[col];
                    stg[col * STG_STRIDE + row] = x / (1.f + __expf(-x));
                }
            }
        }
        __syncthreads();
#pragma unroll
        for (int cl = 0; cl < 16; cl++) {
            int col = warp * 16 + cl;
            int gc = bn + col;
            if (gc < NCAT) {
                float4 val = *(float4*)&stg[col * STG_STRIDE + lane * 4];
                *(float4*)(g_HT + (size_t)gc * B_TOK + bm + lane * 4) = val;
            }
        }
    }
}

// ---------------------------------------------------------------------------
// Kernel: tail5 — slot-per-CTA, 256 threads, 128 tokens, 2 threads/token.
// (verbatim — best known tail at 62.4us)
// ---------------------------------------------------------------------------
#define T5_H1   0                         // 2*64*128 = 16384
#define T5_W2   16384                     // 2*2048
#define T5_W3   20480                     // 2*2048
#define T5_B2   24576                     // 2*32
#define T5_B3   24640                     // 2*64
#define T5_GM   24768                     // 2*64
#define T5_BT   24896                     // 2*64
#define T5_GW   25024                     // 64
#define T5_GB   25088                     // 2
#define T5_FLOATS 25090
#define T5_SMEM (T5_FLOATS * 4)

__global__ void __launch_bounds__(256, 2) tail5_kernel(
    const float* __restrict__ sw2, const float* __restrict__ sb2,
    const float* __restrict__ sw3, const float* __restrict__ sb3,
    const float* __restrict__ sgam, const float* __restrict__ sbet,
    const float* __restrict__ sgw2, const float* __restrict__ sgb2,
    const float* __restrict__ gw2, const float* __restrict__ gb2,
    const float* __restrict__ gw3, const float* __restrict__ gb3,
    const float* __restrict__ ggam, const float* __restrict__ gbet,
    const float* __restrict__ ggw2, const float* __restrict__ ggb2,
    float* __restrict__ out) {
    extern __shared__ float sm[];
    const unsigned FULL = 0xffffffffu;

    const int p    = blockIdx.y;          // 0=group0(e2,3) 1=group1(e4,5) 2=shared(e0,1)
    const int tid  = threadIdx.x;
    const int half = tid & 1;
    const int ltok = tid >> 1;            // 0..127
    const int t0   = blockIdx.x * 128;
    const int tok  = t0 + ltok;
    const int e_base = (p == 2) ? 0 : ((p == 0) ? 2 : 4);
    const int gslot  = (p == 2) ? 0 : (p + 1);

    {
        const float* src = g_HT + (size_t)(e_base * 64) * B_TOK + t0;
#pragma unroll
        for (int k = 0; k < 16; k++) {
            int lin = tid + k * 256;          // 0..4095
            int row = lin >> 5, q = lin & 31;
            float4 val = *(const float4*)(src + (size_t)row * B_TOK + q * 4);
            *(float4*)&sm[T5_H1 + row * 128 + q * 4] = val;
        }
    }
#pragma unroll
    for (int s = 0; s < 2; s++) {
        const int e = e_base + s;
        const float* w2src = (e < 2) ? (sw2 + (size_t)e * 2048) : (gw2 + (size_t)(e - 2) * 2048);
        const float* w3src = (e < 2) ? (sw3 + (size_t)e * 2048) : (gw3 + (size_t)(e - 2) * 2048);
        for (int i = tid; i < 2048; i += 256) {
            sm[T5_W2 + s * 2048 + i] = w2src[i];
            sm[T5_W3 + s * 2048 + i] = w3src[i];
        }
        if (tid < H2) sm[T5_B2 + s * 32 + tid] = (e < 2) ? sb2[e * 32 + tid] : gb2[(e - 2) * 32 + tid];
        if (tid < D_OUT) {
            sm[T5_B3 + s * 64 + tid] = (e < 2) ? sb3[e * 64 + tid]  : gb3[(e - 2) * 64 + tid];
            sm[T5_GM + s * 64 + tid] = (e < 2) ? sgam[e * 64 + tid] : ggam[(e - 2) * 64 + tid];
            sm[T5_BT + s * 64 + tid] = (e < 2) ? sbet[e * 64 + tid] : gbet[(e - 2) * 64 + tid];
        }
    }
    if (tid < 64) sm[T5_GW + tid] = (gslot == 0) ? sgw2[tid] : ggw2[(gslot - 1) * 64 + tid];
    if (tid < 2)  sm[T5_GB + tid] = (gslot == 0) ? sgb2[tid] : ggb2[(gslot - 1) * 2 + tid];
    __syncthreads();

    float wgate2[2];
    {
        float l0 = sm[T5_GB + 0], l1 = sm[T5_GB + 1];
        const float* gbase = g_HT + (size_t)(384 + gslot * 32) * B_TOK + tok;
#pragma unroll 8
        for (int i = 0; i < GH; i++) {
            float hg = gbase[(size_t)i * B_TOK];
            l0 += hg * sm[T5_GW + i * 2];
            l1 += hg * sm[T5_GW + i * 2 + 1];
        }
        float mx = fmaxf(l0, l1);
        float ea = __expf(l0 - mx), eb = __expf(l1 - mx);
        float inv_s = 1.f / (ea + eb);
        wgate2[0] = ea * inv_s;
        wgate2[1] = eb * inv_s;
    }

    float z[32];

#pragma unroll
    for (int s = 0; s < 2; s++) {
        const float* h1b = sm + T5_H1 + s * 8192;
        const float* w2b = sm + T5_W2 + s * 2048 + half * 16;

        float h2[16];
        {
            const float* b2 = sm + T5_B2 + s * 32 + half * 16;
#pragma unroll
            for (int j = 0; j < 16; j++) h2[j] = b2[j];
        }
#pragma unroll 8
        for (int i = 0; i < H1; i++) {
            float a = h1b[i * 128 + ltok];
            const float4* w4 = (const float4*)(w2b + i * 32);
#pragma unroll
            for (int j4 = 0; j4 < 4; j4++) {
                float4 w = w4[j4];
                h2[j4 * 4 + 0] += a * w.x;
                h2[j4 * 4 + 1] += a * w.y;
                h2[j4 * 4 + 2] += a * w.z;
                h2[j4 * 4 + 3] += a * w.w;
            }
        }
#pragma unroll
        for (int j = 0; j < 16; j++) h2[j] = h2[j] / (1.f + __expf(-h2[j]));

        float hlo[16], hhi[16];
#pragma unroll
        for (int j = 0; j < 16; j++) {
            float other = __shfl_xor_sync(FULL, h2[j], 1);
            hlo[j] = half ? other : h2[j];
            hhi[j] = half ? h2[j] : other;
        }

        float o[32];
        {
            const float* b3 = sm + T5_B3 + s * 64 + half * 32;
#pragma unroll
            for (int j = 0; j < 32; j++) o[j] = b3[j];
        }
        const float* w3b = sm + T5_W3 + s * 2048 + half * 32;
#pragma unroll
        for (int k = 0; k < 16; k++) {
            float h = hlo[k];
            const float4* w4 = (const float4*)(w3b + k * 64);
#pragma unroll
            for (int j4 = 0; j4 < 8; j4++) {
                float4 w = w4[j4];
                o[j4 * 4 + 0] += h * w.x;
                o[j4 * 4 + 1] += h * w.y;
                o[j4 * 4 + 2] += h * w.z;
                o[j4 * 4 + 3] += h * w.w;
            }
        }
#pragma unroll
        for (int k = 0; k < 16; k++) {
            float h = hhi[k];
            const float4* w4 = (const float4*)(w3b + (k + 16) * 64);
#pragma unroll
            for (int j4 = 0; j4 < 8; j4++) {
                float4 w = w4[j4];
                o[j4 * 4 + 0] += h * w.x;
                o[j4 * 4 + 1] += h * w.y;
                o[j4 * 4 + 2] += h * w.z;
                o[j4 * 4 + 3] += h * w.w;
            }
        }

        float s1 = 0.f;
#pragma unroll
        for (int j = 0; j < 32; j++) s1 += o[j];
        s1 += __shfl_xor_sync(FULL, s1, 1);
        float mu = s1 * (1.f / 64.f);
        float s2 = 0.f;
#pragma unroll
        for (int j = 0; j < 32; j++) { float d = o[j] - mu; s2 += d * d; }
        s2 += __shfl_xor_sync(FULL, s2, 1);
        float x = s2 * (1.f / 64.f) + LN_EPS;
        float rinv = rsqrtf(x);
        rinv = rinv * (1.5f - 0.5f * x * rinv * rinv);

        const float wg = wgate2[s];
        const float* gm = sm + T5_GM + s * 64 + half * 32;
        const float* bt = sm + T5_BT + s * 64 + half * 32;
        if (s == 0) {
#pragma unroll
            for (int j = 0; j < 32; j++)
                z[j] = wg * (gm[j] * (o[j] - mu) * rinv + bt[j]);
        } else {
#pragma unroll
            for (int j = 0; j < 32; j++)
                z[j] += wg * (gm[j] * (o[j] - mu) * rinv + bt[j]);
        }
    }

    float* obase = out + ((size_t)p * B_TOK + tok) * D_OUT + half * 32;
#pragma unroll
    for (int j4 = 0; j4 < 8; j4++) {
        float4 y;
        y.x = z[j4 * 4 + 0]; y.y = z[j4 * 4 + 1];
        y.z = z[j4 * 4 + 2]; y.w = z[j4 * 4 + 3];
        *(float4*)(obase + j4 * 4) = y;
    }
}

// ---------------------------------------------------------------------------
// Launch
// ---------------------------------------------------------------------------
extern "C" void kernel_launch(void* const* d_in, const int* in_sizes, int n_in,
                              void* d_out, int out_size) {
    (void)in_sizes; (void)n_in; (void)out_size;
    const float* v    = (const float*)d_in[0];
    const float* sw1  = (const float*)d_in[1];
    const float* sb1  = (const float*)d_in[2];
    const float* sw2  = (const float*)d_in[3];
    const float* sb2  = (const float*)d_in[4];
    const float* sw3  = (const float*)d_in[5];
    const float* sb3  = (const float*)d_in[6];
    const float* sgam = (const float*)d_in[7];
    const float* sbet = (const float*)d_in[8];
    const float* sgw1 = (const float*)d_in[9];
    const float* sgb1 = (const float*)d_in[10];
    const float* sgw2 = (const float*)d_in[11];
    const float* sgb2 = (const float*)d_in[12];
    const float* gw1  = (const float*)d_in[13];
    const float* gb1  = (const float*)d_in[14];
    const float* gw2  = (const float*)d_in[15];
    const float* gb2  = (const float*)d_in[16];
    const float* gw3  = (const float*)d_in[17];
    const float* gb3  = (const float*)d_in[18];
    const float* ggam = (const float*)d_in[19];
    const float* gbet = (const float*)d_in[20];
    const float* ggw1 = (const float*)d_in[21];
    const float* ggb1 = (const float*)d_in[22];
    const float* ggw2 = (const float*)d_in[23];
    const float* ggb2 = (const float*)d_in[24];
    float* out = (float*)d_out;

    prep_kernel<<<CONV_BLOCKS + (NCATP * D_IN) / 256, 256>>>(
        v, sw1, sb1, gw1, gb1, sgw1, sgb1, ggw1, ggb1);

    cudaFuncSetAttribute(gemm1_mma_kernel, cudaFuncAttributeMaxDynamicSharedMemorySize, GEMM_SMEM);
    dim3 g1(NCATP / 128, B_TOK / 128);
    gemm1_mma_kernel<<<g1, 256, GEMM_SMEM>>>();

    cudaFuncSetAttribute(tail5_kernel, cudaFuncAttributeMaxDynamicSharedMemorySize, T5_SMEM);
    dim3 g2(B_TOK / 128, 3);
    tail5_kernel<<<g2, 256, T5_SMEM>>>(sw2, sb2, sw3, sb3, sgam, sbet, sgw2, sgb2,
                                       gw2, gb2, gw3, gb3, ggam, gbet, ggw2, ggb2, out);
}

// round 15
// speedup vs baseline: 2.8700x; 1.4829x over previous
#include <cuda_runtime.h>
#include <cuda_fp16.h>
#include <math.h>
#include <stddef.h>
#include <stdint.h>

// ---------------------------------------------------------------------------
// Problem constants
// ---------------------------------------------------------------------------
#define B_TOK   16384
#define D_IN    512
#define D_OUT   64
#define H1      64
#define H2      32
#define GH      32
#define NEXP    6
#define NCAT    480
#define NCATP   512
#define LN_EPS  1e-5f

// ---------------------------------------------------------------------------
// Device scratch
// ---------------------------------------------------------------------------
__device__ __align__(16) __half g_vh[(size_t)B_TOK * D_IN];    // fp16(v)
__device__ __align__(16) __half g_wh[NCATP * D_IN];            // [n][k] fp16
__device__ float g_bc[NCATP];
__device__ __align__(16) __half g_Hh[(size_t)B_TOK * NCATP];   // H fp16 [token][col]

__device__ __forceinline__ uint32_t smem_u32(const void* p) {
    uint32_t a;
    asm("{ .reg .u64 t; cvta.to.shared.u64 t, %1; cvt.u32.u64 %0, t; }" : "=r"(a) : "l"(p));
    return a;
}

// ---------------------------------------------------------------------------
// Kernel: prep = conv_v (blocks 0..8191) + pack_w (blocks 8192..9215)
// ---------------------------------------------------------------------------
#define CONV_BLOCKS 8192
__global__ __launch_bounds__(256) void prep_kernel(
    const float* __restrict__ v,
    const float* __restrict__ sw1, const float* __restrict__ sb1,
    const float* __restrict__ gw1, const float* __restrict__ gb1,
    const float* __restrict__ sgw1, const float* __restrict__ sgb1,
    const float* __restrict__ ggw1, const float* __restrict__ ggb1) {
    if (blockIdx.x < CONV_BLOCKS) {
        size_t i = ((size_t)blockIdx.x * 256 + threadIdx.x) * 4;
        float4 x = *(const float4*)(v + i);
        __half2* ph = (__half2*)(g_vh + i);
        ph[0] = __floats2half2_rn(x.x, x.y);
        ph[1] = __floats2half2_rn(x.z, x.w);
    } else {
        int idx = (blockIdx.x - CONV_BLOCKS) * 256 + threadIdx.x;   // over 512*512
        int n = idx >> 9, k = idx & 511;
        float w = 0.f;
        if (n < 384) {
            int e = n >> 6, j = n & 63;
            w = (e < 2) ? sw1[((size_t)e * D_IN + k) * 64 + j]
                        : gw1[((size_t)(e - 2) * D_IN + k) * 64 + j];
        } else if (n < 480) {
            int m = n - 384, s = m >> 5, j = m & 31;
            w = (s == 0) ? sgw1[k * 32 + j]
                         : ggw1[((size_t)(s - 1) * D_IN + k) * 32 + j];
        }
        g_wh[idx] = __float2half_rn(w);
        if (idx < NCATP) {
            float b = 0.f;
            if (idx < 384) {
                int e = idx >> 6, j = idx & 63;
                b = (e < 2) ? sb1[e * 64 + j] : gb1[(e - 2) * 64 + j];
            } else if (idx < 480) {
                int m = idx - 384, s = m >> 5, j = m & 31;
                b = (s == 0) ? sgb1[j] : ggb1[(s - 1) * GH + j];
            }
            g_bc[idx] = b;
        }
    }
}

// ---------------------------------------------------------------------------
// Kernel: H = silu(v @ W + b) fp16 token-major, via single-pass fp16 mma.sync.
// 3-stage cp.async pipeline (distance 2), K chunks of 32, 1 barrier/chunk.
// CTA 128x128, warps 2(M)x4(N). XOR swizzle seg' = seg ^ ((row>>1)&3).
// ---------------------------------------------------------------------------
#define KCH2    32
#define OPB     (128 * 64)                  // 8192 per operand per stage
#define STAGE_B (2 * OPB)                   // 16384 (A, B)
#define NSTAGE  3
#define SMO_BIAS (NSTAGE * STAGE_B)         // 49152 (> hstage 128*272 = 34816)
#define GEMM_SMEM (SMO_BIAS + 512)
#define NCHUNK  (D_IN / KCH2)               // 16

#define CPASYNC16(dst, src) \
    asm volatile("cp.async.cg.shared.global [%0], [%1], 16;" :: "r"(dst), "l"(src))

__device__ __forceinline__ void ldsm_x4(uint32_t* r, uint32_t a) {
    asm volatile("ldmatrix.sync.aligned.m8n8.x4.shared.b16 {%0,%1,%2,%3}, [%4];"
                 : "=r"(r[0]), "=r"(r[1]), "=r"(r[2]), "=r"(r[3]) : "r"(a));
}
__device__ __forceinline__ void ldsm_x2t(uint32_t* r, uint32_t a) {
    asm volatile("ldmatrix.sync.aligned.m8n8.x2.trans.shared.b16 {%0,%1}, [%2];"
                 : "=r"(r[0]), "=r"(r[1]) : "r"(a));
}
__device__ __forceinline__ void mma_f16(float* c, const uint32_t* a, uint32_t b0, uint32_t b1) {
    asm volatile(
        "mma.sync.aligned.m16n8k16.row.col.f32.f16.f16.f32 "
        "{%0,%1,%2,%3}, {%4,%5,%6,%7}, {%8,%9}, {%0,%1,%2,%3};"
        : "+f"(c[0]), "+f"(c[1]), "+f"(c[2]), "+f"(c[3])
        : "r"(a[0]), "r"(a[1]), "r"(a[2]), "r"(a[3]), "r"(b0), "r"(b1));
}
__device__ __forceinline__ float silu_f(float x) { return x / (1.f + __expf(-x)); }

__global__ void __launch_bounds__(256, 2) gemm1_mma_kernel() {
    extern __shared__ char smem[];
    const uint32_t sb = smem_u32(smem);
    const int tid  = threadIdx.x;
    const int lane = tid & 31;
    const int warp = tid >> 5;
    const int wm = warp >> 2;
    const int wn = warp & 3;
    const int bm = blockIdx.y * 128;
    const int bn = blockIdx.x * 128;

    if (tid < 128) ((float*)(smem + SMO_BIAS))[tid] = g_bc[bn + tid];

    const int r0 = tid >> 2, r1 = r0 + 64;
    const int seg = tid & 3;
    const uint32_t d0 = (uint32_t)(r0 * 64 + ((seg ^ ((r0 >> 1) & 3)) << 4));
    const uint32_t d1 = (uint32_t)(r1 * 64 + ((seg ^ ((r1 >> 1) & 3)) << 4));
    const int selem = seg * 8;

    const int mi = lane >> 3;
    const int a_row = (lane & 7) + ((mi & 1) << 3);
    const int akb4  = (mi >= 2) ? 1 : 0;
    const int b_row = (lane & 7) + ((mi >= 2) ? 8 : 0);
    const int bkb4  = (mi & 1) ? 1 : 0;
    const int arsw  = (a_row >> 1) & 3;
    const int brsw  = (b_row >> 1) & 3;

    float acc[4][4][4];
#pragma unroll
    for (int i = 0; i < 4; i++)
#pragma unroll
        for (int j = 0; j < 4; j++)
#pragma unroll
            for (int u = 0; u < 4; u++) acc[i][j][u] = 0.f;

    auto load_chunk = [&](int ch, int stg) {
        const int k0 = ch * KCH2;
        const uint32_t base = sb + stg * STAGE_B;
        const __half* sa0 = g_vh + (size_t)(bm + r0) * D_IN + k0 + selem;
        const __half* sa1 = g_vh + (size_t)(bm + r1) * D_IN + k0 + selem;
        const __half* sh0 = g_wh + (size_t)(bn + r0) * D_IN + k0 + selem;
        const __half* sh1 = g_wh + (size_t)(bn + r1) * D_IN + k0 + selem;
        CPASYNC16(base + 0 * OPB + d0, sa0);
        CPASYNC16(base + 0 * OPB + d1, sa1);
        CPASYNC16(base + 1 * OPB + d0, sh0);
        CPASYNC16(base + 1 * OPB + d1, sh1);
    };

    load_chunk(0, 0);
    asm volatile("cp.async.commit_group;");
    load_chunk(1, 1);
    asm volatile("cp.async.commit_group;");

    for (int ch = 0; ch < NCHUNK; ch++) {
        if (ch < NCHUNK - 1) {
            asm volatile("cp.async.wait_group 1;");
        } else {
            asm volatile("cp.async.wait_group 0;");
        }
        __syncthreads();

        if (ch + 2 < NCHUNK) {
            load_chunk(ch + 2, (ch + 2) % NSTAGE);
            asm volatile("cp.async.commit_group;");
        }

        const uint32_t stgb  = sb + (ch % NSTAGE) * STAGE_B;
        const uint32_t aBase = stgb + 0 * OPB + (uint32_t)((wm * 64 + a_row) * 64);
        const uint32_t bBase = stgb + 1 * OPB + (uint32_t)((wn * 32 + b_row) * 64);

#pragma unroll
        for (int kt = 0; kt < 2; kt++) {
            const uint32_t aoff = (uint32_t)(((kt * 2 + akb4) ^ arsw) << 4);
            const uint32_t boff = (uint32_t)(((kt * 2 + bkb4) ^ brsw) << 4);
            uint32_t ah[4][4], bh[2][4];
#pragma unroll
            for (int mt = 0; mt < 4; mt++)
                ldsm_x4(ah[mt], aBase + mt * 1024 + aoff);
#pragma unroll
            for (int h = 0; h < 2; h++)
                ldsm_x4(bh[h], bBase + h * 1024 + boff);
#pragma unroll
            for (int mt = 0; mt < 4; mt++)
#pragma unroll
                for (int nt = 0; nt < 4; nt++)
                    mma_f16(acc[mt][nt], ah[mt], bh[nt >> 1][(nt & 1) * 2], bh[nt >> 1][(nt & 1) * 2 + 1]);
        }
    }
    __syncthreads();

    // Epilogue: bias + silu -> half stage [row][136] -> coalesced g_Hh rows
    {
        __half* stg = (__half*)smem;
        const float* bias = (const float*)(smem + SMO_BIAS);
#pragma unroll
        for (int mt = 0; mt < 4; mt++) {
#pragma unroll
            for (int nt = 0; nt < 4; nt++) {
                int r = wm * 64 + mt * 16 + (lane >> 2);
                int c0 = wn * 32 + nt * 8 + 2 * (lane & 3);
                float b0 = bias[c0], b1 = bias[c0 + 1];
                float y0 = silu_f(acc[mt][nt][0] + b0);
                float y1 = silu_f(acc[mt][nt][1] + b1);
                float y2 = silu_f(acc[mt][nt][2] + b0);
                float y3 = silu_f(acc[mt][nt][3] + b1);
                *(__half2*)(stg + r * 136 + c0)       = __floats2half2_rn(y0, y1);
                *(__half2*)(stg + (r + 8) * 136 + c0) = __floats2half2_rn(y2, y3);
            }
        }
        __syncthreads();
#pragma unroll
        for (int k = 0; k < 8; k++) {
            int lin = tid + k * 256;    // 0..2047
            int row = lin >> 4, s = lin & 15;
            uint4 val = *(uint4*)((char*)smem + row * 272 + s * 16);
            *(uint4*)(g_Hh + (size_t)(bm + row) * NCATP + bn + s * 8) = val;
        }
    }
}

// ---------------------------------------------------------------------------
// Kernel: tail7 — tensor-core tail. grid (B/128, 3), 256 threads (8 warps).
// warps: ws = warp>>2 (expert of slot), wr = warp&3 (32-token strip).
// layer2 MMA -> silu -> h2 fp16 smem -> layer3 MMA -> +b3 -> LN -> gated
// accumulate in smem zacc (ws0 write, ws1 add) -> coalesced fp32 out.
// ---------------------------------------------------------------------------
// smem offsets (bytes)
#define A7      0                        // 32768 : A [128][256B] xor-swz seg^(row&7)
#define H27     32768                    // 20480 : 2 x [128 tok][80B] (32 half + pad)
#define W27     53248                    // 10240 : 2 x [64 k][80B]  (32 half + pad)
#define W37     63488                    // 9216  : 2 x [32 k][144B] (64 half + pad)
#define ZAC7    72704                    // 34816 : [128][68] f32
#define WG7     107520                   // 1024  : [128][2] f32 gate weights
#define PB2     108544                   // 256   : 2 x 32 f32
#define PB3     108800                   // 512   : 2 x 64 f32
#define PGM     109312                   // 512
#define PBT     109824                   // 512
#define PGW     110336                   // 256   : 64 f32
#define PGB     110592                   // 8     : 2 f32
#define T7_SMEM 110600

__global__ void __launch_bounds__(256, 2) tail7_kernel(
    const float* __restrict__ sw2, const float* __restrict__ sb2,
    const float* __restrict__ sw3, const float* __restrict__ sb3,
    const float* __restrict__ sgam, const float* __restrict__ sbet,
    const float* __restrict__ sgw2, const float* __restrict__ sgb2,
    const float* __restrict__ gw2, const float* __restrict__ gb2,
    const float* __restrict__ gw3, const float* __restrict__ gb3,
    const float* __restrict__ ggam, const float* __restrict__ gbet,
    const float* __restrict__ ggw2, const float* __restrict__ ggb2,
    float* __restrict__ out) {
    extern __shared__ char smem[];
    const uint32_t sb = smem_u32(smem);
    const int tid  = threadIdx.x;
    const int lane = tid & 31;
    const int warp = tid >> 5;
    const int ws = warp >> 2;             // expert within slot
    const int wr = warp & 3;              // token strip (32 rows)
    const int p  = blockIdx.y;            // 0=group0(e2,3) 1=group1(e4,5) 2=shared(e0,1)
    const int t0 = blockIdx.x * 128;
    const int e_base = (p == 2) ? 0 : ((p == 0) ? 2 : 4);
    const int gslot  = (p == 2) ? 0 : (p + 1);

    // ---- stage A: rows t0..t0+127, cols e_base*64..+127 (256B/row) ----
    {
        const __half* src = g_Hh + (size_t)t0 * NCATP + e_base * 64;
#pragma unroll
        for (int k = 0; k < 8; k++) {
            int lin = tid + k * 256;
            int row = lin >> 4, s = lin & 15;
            uint4 val = *(const uint4*)(src + (size_t)row * NCATP + s * 8);
            *(uint4*)(smem + A7 + row * 256 + ((s ^ (row & 7)) << 4)) = val;
        }
    }
    // ---- stage weights (fp32 -> fp16) + params ----
#pragma unroll
    for (int s = 0; s < 2; s++) {
        const int e = e_base + s;
        const float* w2src = (e < 2) ? (sw2 + (size_t)e * 2048) : (gw2 + (size_t)(e - 2) * 2048);
        const float* w3src = (e < 2) ? (sw3 + (size_t)e * 2048) : (gw3 + (size_t)(e - 2) * 2048);
        __half* w2d = (__half*)(smem + W27 + s * 5120);
        __half* w3d = (__half*)(smem + W37 + s * 4608);
        for (int i = tid; i < 2048; i += 256) {
            w2d[(i >> 5) * 40 + (i & 31)] = __float2half_rn(w2src[i]);
            w3d[(i >> 6) * 72 + (i & 63)] = __float2half_rn(w3src[i]);
        }
        if (tid < H2) ((float*)(smem + PB2))[s * 32 + tid] =
            (e < 2) ? sb2[e * 32 + tid] : gb2[(e - 2) * 32 + tid];
        if (tid < D_OUT) {
            ((float*)(smem + PB3))[s * 64 + tid] = (e < 2) ? sb3[e * 64 + tid]  : gb3[(e - 2) * 64 + tid];
            ((float*)(smem + PGM))[s * 64 + tid] = (e < 2) ? sgam[e * 64 + tid] : ggam[(e - 2) * 64 + tid];
            ((float*)(smem + PBT))[s * 64 + tid] = (e < 2) ? sbet[e * 64 + tid] : gbet[(e - 2) * 64 + tid];
        }
    }
    if (tid < 64) ((float*)(smem + PGW))[tid] = (gslot == 0) ? sgw2[tid] : ggw2[(gslot - 1) * 64 + tid];
    if (tid < 2)  ((float*)(smem + PGB))[tid] = (gslot == 0) ? sgb2[tid] : ggb2[(gslot - 1) * 2 + tid];
    __syncthreads();

    // ---- gate softmax (one thread per token) ----
    if (tid < 128) {
        const __half2* gp = (const __half2*)(g_Hh + (size_t)(t0 + tid) * NCATP + 384 + gslot * 32);
        const float* gw = (const float*)(smem + PGW);
        float l0 = ((const float*)(smem + PGB))[0];
        float l1 = ((const float*)(smem + PGB))[1];
#pragma unroll
        for (int i = 0; i < 16; i++) {
            float2 h = __half22float2(gp[i]);
            l0 += h.x * gw[(2 * i) * 2]     + h.y * gw[(2 * i + 1) * 2];
            l1 += h.x * gw[(2 * i) * 2 + 1] + h.y * gw[(2 * i + 1) * 2 + 1];
        }
        float mx = fmaxf(l0, l1);
        float ea = __expf(l0 - mx), eb = __expf(l1 - mx);
        float inv = 1.f / (ea + eb);
        ((float2*)(smem + WG7))[tid] = make_float2(ea * inv, eb * inv);
    }

    // ldmatrix lane geometry (A fragments)
    const int mi = lane >> 3;
    const int a_row = (lane & 7) + ((mi & 1) << 3);
    const int akb = (mi >= 2) ? 1 : 0;          // k 16B-seg select
    const int tokb = wr * 32;

    // ---- layer2: c2[128x32] = A[128x64(e)] @ W2[64x32], per-warp 32x32 ----
    float c2[2][4][4];
#pragma unroll
    for (int i = 0; i < 2; i++)
#pragma unroll
        for (int j = 0; j < 4; j++)
#pragma unroll
            for (int u = 0; u < 4; u++) c2[i][j][u] = 0.f;
    {
        const uint32_t aA = sb + A7 + (uint32_t)((tokb + a_row) * 256);
        const uint32_t bA = sb + W27 + (uint32_t)(ws * 5120 + (lane & 15) * 80);
#pragma unroll
        for (int kt = 0; kt < 4; kt++) {
            uint32_t aseg = (uint32_t)(((ws * 8 + kt * 2 + akb) ^ (lane & 7)) << 4);
            uint32_t a0[4], a1[4];
            ldsm_x4(a0, aA + aseg);
            ldsm_x4(a1, aA + 4096 + aseg);      // mt=1: +16 rows * 256B
#pragma unroll
            for (int nt = 0; nt < 4; nt++) {
                uint32_t b[2];
                ldsm_x2t(b, bA + (uint32_t)(kt * 16 * 80 + nt * 16));
                mma_f16(c2[0][nt], a0, b[0], b[1]);
                mma_f16(c2[1][nt], a1, b[0], b[1]);
            }
        }
    }
    // bias + silu -> h2 fp16 smem [tok][80B]
    {
        const float* b2v = (const float*)(smem + PB2) + ws * 32;
        char* h2b = smem + H27 + ws * 10240;
#pragma unroll
        for (int mt = 0; mt < 2; mt++)
#pragma unroll
            for (int nt = 0; nt < 4; nt++) {
                int c0 = nt * 8 + 2 * (lane & 3);
                int r  = tokb + mt * 16 + (lane >> 2);
                float b0 = b2v[c0], b1 = b2v[c0 + 1];
                float y0 = silu_f(c2[mt][nt][0] + b0);
                float y1 = silu_f(c2[mt][nt][1] + b1);
                float y2 = silu_f(c2[mt][nt][2] + b0);
                float y3 = silu_f(c2[mt][nt][3] + b1);
                *(__half2*)(h2b + r * 80 + c0 * 2)       = __floats2half2_rn(y0, y1);
                *(__half2*)(h2b + (r + 8) * 80 + c0 * 2) = __floats2half2_rn(y2, y3);
            }
    }
    __syncthreads();

    // ---- layer3: c3[128x64] = h2[128x32] @ W3[32x64], per-warp 32x64 ----
    float c3[2][8][4];
#pragma unroll
    for (int i = 0; i < 2; i++)
#pragma unroll
        for (int j = 0; j < 8; j++)
#pragma unroll
            for (int u = 0; u < 4; u++) c3[i][j][u] = 0.f;
    {
        const uint32_t aA = sb + H27 + (uint32_t)(ws * 10240 + (tokb + a_row) * 80);
        const uint32_t bA = sb + W37 + (uint32_t)(ws * 4608 + (lane & 15) * 144);
#pragma unroll
        for (int kt = 0; kt < 2; kt++) {
            uint32_t aoff = (uint32_t)(kt * 32 + akb * 16);
            uint32_t a0[4], a1[4];
            ldsm_x4(a0, aA + aoff);
            ldsm_x4(a1, aA + 16 * 80 + aoff);
#pragma unroll
            for (int nt = 0; nt < 8; nt++) {
                uint32_t b[2];
                ldsm_x2t(b, bA + (uint32_t)(kt * 16 * 144 + nt * 16));
                mma_f16(c3[0][nt], a0, b[0], b[1]);
                mma_f16(c3[1][nt], a1, b[0], b[1]);
            }
        }
    }

    // ---- +b3, LN, gated accumulate into zacc ----
    const float* b3v = (const float*)(smem + PB3) + ws * 64;
    const float* gmv = (const float*)(smem + PGM) + ws * 64;
    const float* btv = (const float*)(smem + PBT) + ws * 64;
    const unsigned FULL = 0xffffffffu;

    auto ln_acc = [&](bool add) {
#pragma unroll
        for (int mt = 0; mt < 2; mt++)
#pragma unroll
            for (int rh = 0; rh < 2; rh++) {
                float s1 = 0.f;
#pragma unroll
                for (int nt = 0; nt < 8; nt++) {
                    int c0 = nt * 8 + 2 * (lane & 3);
                    c3[mt][nt][rh * 2]     += (rh == 0 && false) ? 0.f : 0.f;  // no-op
                    float v0 = c3[mt][nt][rh * 2]     + b3v[c0];
                    float v1 = c3[mt][nt][rh * 2 + 1] + b3v[c0 + 1];
                    s1 += v0 + v1;
                }
                s1 += __shfl_xor_sync(FULL, s1, 1);
                s1 += __shfl_xor_sync(FULL, s1, 2);
                float mu = s1 * (1.f / 64.f);
                float s2 = 0.f;
#pragma unroll
                for (int nt = 0; nt < 8; nt++) {
                    int c0 = nt * 8 + 2 * (lane & 3);
                    float d0 = c3[mt][nt][rh * 2]     + b3v[c0]     - mu;
                    float d1 = c3[mt][nt][rh * 2 + 1] + b3v[c0 + 1] - mu;
                    s2 += d0 * d0 + d1 * d1;
                }
                s2 += __shfl_xor_sync(FULL, s2, 1);
                s2 += __shfl_xor_sync(FULL, s2, 2);
                float x = s2 * (1.f / 64.f) + LN_EPS;
                float rinv = rsqrtf(x);
                rinv = rinv * (1.5f - 0.5f * x * rinv * rinv);

                int row = tokb + mt * 16 + (lane >> 2) + rh * 8;
                float wg = ((const float*)(smem + WG7))[row * 2 + ws];
                float* zr = (float*)(smem + ZAC7) + row * 68;
#pragma unroll
                for (int nt = 0; nt < 8; nt++) {
                    int c0 = nt * 8 + 2 * (lane & 3);
                    float d0 = c3[mt][nt][rh * 2]     + b3v[c0]     - mu;
                    float d1 = c3[mt][nt][rh * 2 + 1] + b3v[c0 + 1] - mu;
                    float z0 = wg * (gmv[c0] * d0 * rinv + btv[c0]);
                    float z1 = wg * (gmv[c0 + 1] * d1 * rinv + btv[c0 + 1]);
                    if (add) { zr[c0] += z0; zr[c0 + 1] += z1; }
                    else     { zr[c0]  = z0; zr[c0 + 1]  = z1; }
                }
            }
    };

    if (ws == 0) ln_acc(false);
    __syncthreads();
    if (ws == 1) ln_acc(true);
    __syncthreads();

    // ---- coalesced fp32 store ----
    float* ob = out + ((size_t)p * B_TOK + t0) * D_OUT;
#pragma unroll
    for (int k = 0; k < 8; k++) {
        int lin = tid + k * 256;            // 0..2047 float4
        int row = lin >> 4, c4 = (lin & 15) * 4;
        float4 v = *(float4*)((float*)(smem + ZAC7) + row * 68 + c4);
        *(float4*)(ob + (size_t)row * D_OUT + c4) = v;
    }
}

// ---------------------------------------------------------------------------
// Launch
// ---------------------------------------------------------------------------
extern "C" void kernel_launch(void* const* d_in, const int* in_sizes, int n_in,
                              void* d_out, int out_size) {
    (void)in_sizes; (void)n_in; (void)out_size;
    const float* v    = (const float*)d_in[0];
    const float* sw1  = (const float*)d_in[1];
    const float* sb1  = (const float*)d_in[2];
    const float* sw2  = (const float*)d_in[3];
    const float* sb2  = (const float*)d_in[4];
    const float* sw3  = (const float*)d_in[5];
    const float* sb3  = (const float*)d_in[6];
    const float* sgam = (const float*)d_in[7];
    const float* sbet = (const float*)d_in[8];
    const float* sgw1 = (const float*)d_in[9];
    const float* sgb1 = (const float*)d_in[10];
    const float* sgw2 = (const float*)d_in[11];
    const float* sgb2 = (const float*)d_in[12];
    const float* gw1  = (const float*)d_in[13];
    const float* gb1  = (const float*)d_in[14];
    const float* gw2  = (const float*)d_in[15];
    const float* gb2  = (const float*)d_in[16];
    const float* gw3  = (const float*)d_in[17];
    const float* gb3  = (const float*)d_in[18];
    const float* ggam = (const float*)d_in[19];
    const float* gbet = (const float*)d_in[20];
    const float* ggw1 = (const float*)d_in[21];
    const float* ggb1 = (const float*)d_in[22];
    const float* ggw2 = (const float*)d_in[23];
    const float* ggb2 = (const float*)d_in[24];
    float* out = (float*)d_out;

    prep_kernel<<<CONV_BLOCKS + (NCATP * D_IN) / 256, 256>>>(
        v, sw1, sb1, gw1, gb1, sgw1, sgb1, ggw1, ggb1);

    cudaFuncSetAttribute(gemm1_mma_kernel, cudaFuncAttributeMaxDynamicSharedMemorySize, GEMM_SMEM);
    dim3 g1(NCATP / 128, B_TOK / 128);
    gemm1_mma_kernel<<<g1, 256, GEMM_SMEM>>>();

    cudaFuncSetAttribute(tail7_kernel, cudaFuncAttributeMaxDynamicSharedMemorySize, T7_SMEM);
    dim3 g2(B_TOK / 128, 3);
    tail7_kernel<<<g2, 256, T7_SMEM>>>(sw2, sb2, sw3, sb3, sgam, sbet, sgw2, sgb2,
                                       gw2, gb2, gw3, gb3, ggam, gbet, ggw2, ggb2, out);
}

// round 16
// speedup vs baseline: 2.9205x; 1.0176x over previous
#include <cuda_runtime.h>
#include <cuda_fp16.h>
#include <math.h>
#include <stddef.h>
#include <stdint.h>

// ---------------------------------------------------------------------------
// Problem constants
// ---------------------------------------------------------------------------
#define B_TOK   16384
#define D_IN    512
#define D_OUT   64
#define H1      64
#define H2      32
#define GH      32
#define NEXP    6
#define NCAT    480
#define NCATP   512
#define LN_EPS  1e-5f

// ---------------------------------------------------------------------------
// Device scratch
// ---------------------------------------------------------------------------
__device__ __align__(16) __half g_vh[(size_t)B_TOK * D_IN];    // fp16(v)
__device__ __align__(16) __half g_wh[NCATP * D_IN];            // [n][k] fp16
__device__ float g_bc[NCATP];
__device__ __align__(16) __half g_Hh[(size_t)B_TOK * NCATP];   // H fp16 [token][col]

__device__ __forceinline__ uint32_t smem_u32(const void* p) {
    uint32_t a;
    asm("{ .reg .u64 t; cvta.to.shared.u64 t, %1; cvt.u32.u64 %0, t; }" : "=r"(a) : "l"(p));
    return a;
}

// ---------------------------------------------------------------------------
// Kernel: prep = conv_v (blocks 0..2047, 4 float4/thread for MLP) +
//                pack_w (blocks 2048..2303, 4 elems/thread)
// ---------------------------------------------------------------------------
#define CONV_BLOCKS 2048
__global__ __launch_bounds__(256) void prep_kernel(
    const float* __restrict__ v,
    const float* __restrict__ sw1, const float* __restrict__ sb1,
    const float* __restrict__ gw1, const float* __restrict__ gb1,
    const float* __restrict__ sgw1, const float* __restrict__ sgb1,
    const float* __restrict__ ggw1, const float* __restrict__ ggb1) {
    if (blockIdx.x < CONV_BLOCKS) {
        size_t base = (size_t)blockIdx.x * 1024 + threadIdx.x;   // float4 index
#pragma unroll
        for (int k = 0; k < 4; k++) {
            size_t i = (base + k * 256) * 4;
            float4 x = *(const float4*)(v + i);
            __half2* ph = (__half2*)(g_vh + i);
            ph[0] = __floats2half2_rn(x.x, x.y);
            ph[1] = __floats2half2_rn(x.z, x.w);
        }
    } else {
        int base = (blockIdx.x - CONV_BLOCKS) * 1024 + threadIdx.x;
#pragma unroll
        for (int u = 0; u < 4; u++) {
            int idx = base + u * 256;                            // over 512*512
            int n = idx >> 9, k = idx & 511;
            float w = 0.f;
            if (n < 384) {
                int e = n >> 6, j = n & 63;
                w = (e < 2) ? sw1[((size_t)e * D_IN + k) * 64 + j]
                            : gw1[((size_t)(e - 2) * D_IN + k) * 64 + j];
            } else if (n < 480) {
                int m = n - 384, s = m >> 5, j = m & 31;
                w = (s == 0) ? sgw1[k * 32 + j]
                             : ggw1[((size_t)(s - 1) * D_IN + k) * 32 + j];
            }
            g_wh[idx] = __float2half_rn(w);
            if (idx < NCATP) {
                float b = 0.f;
                if (idx < 384) {
                    int e = idx >> 6, j = idx & 63;
                    b = (e < 2) ? sb1[e * 64 + j] : gb1[(e - 2) * 64 + j];
                } else if (idx < 480) {
                    int m = idx - 384, s = m >> 5, j = m & 31;
                    b = (s == 0) ? sgb1[j] : ggb1[(s - 1) * GH + j];
                }
                g_bc[idx] = b;
            }
        }
    }
}

// ---------------------------------------------------------------------------
// Kernel: H = silu(v @ W + b) fp16 token-major, single-pass fp16 mma.sync.
// 3-stage cp.async pipeline (distance 2), K chunks of 64, 1 barrier/chunk.
// CTA 128x128, warps 2(M)x4(N). XOR swizzle seg' = seg ^ (row&7) on 128B rows.
// ---------------------------------------------------------------------------
#define KCH2    64
#define OPB     (128 * 128)                 // 16384 per operand per stage
#define STAGE_B (2 * OPB)                   // 32768 (A, B)
#define NSTAGE  3
#define SMO_BIAS (NSTAGE * STAGE_B)         // 98304 (> hstage 128*272 = 34816)
#define GEMM_SMEM (SMO_BIAS + 512)
#define NCHUNK  (D_IN / KCH2)               // 8

#define CPASYNC16(dst, src) \
    asm volatile("cp.async.cg.shared.global [%0], [%1], 16;" :: "r"(dst), "l"(src))

__device__ __forceinline__ void ldsm_x4(uint32_t* r, uint32_t a) {
    asm volatile("ldmatrix.sync.aligned.m8n8.x4.shared.b16 {%0,%1,%2,%3}, [%4];"
                 : "=r"(r[0]), "=r"(r[1]), "=r"(r[2]), "=r"(r[3]) : "r"(a));
}
__device__ __forceinline__ void ldsm_x2t(uint32_t* r, uint32_t a) {
    asm volatile("ldmatrix.sync.aligned.m8n8.x2.trans.shared.b16 {%0,%1}, [%2];"
                 : "=r"(r[0]), "=r"(r[1]) : "r"(a));
}
__device__ __forceinline__ void mma_f16(float* c, const uint32_t* a, uint32_t b0, uint32_t b1) {
    asm volatile(
        "mma.sync.aligned.m16n8k16.row.col.f32.f16.f16.f32 "
        "{%0,%1,%2,%3}, {%4,%5,%6,%7}, {%8,%9}, {%0,%1,%2,%3};"
        : "+f"(c[0]), "+f"(c[1]), "+f"(c[2]), "+f"(c[3])
        : "r"(a[0]), "r"(a[1]), "r"(a[2]), "r"(a[3]), "r"(b0), "r"(b1));
}
__device__ __forceinline__ float silu_f(float x) { return x / (1.f + __expf(-x)); }

__global__ void __launch_bounds__(256, 2) gemm1_mma_kernel() {
    extern __shared__ char smem[];
    const uint32_t sb = smem_u32(smem);
    const int tid  = threadIdx.x;
    const int lane = tid & 31;
    const int warp = tid >> 5;
    const int wm = warp >> 2;
    const int wn = warp & 3;
    const int bm = blockIdx.y * 128;
    const int bn = blockIdx.x * 128;

    if (tid < 128) ((float*)(smem + SMO_BIAS))[tid] = g_bc[bn + tid];

    // cp.async geometry: per operand 128 rows x 8 segs of 16B; 4 rows/thread.
    const int r0  = tid >> 3;               // 0..31
    const int seg = tid & 7;
    const uint32_t sw = (uint32_t)((seg ^ (r0 & 7)) << 4);   // (r0+32j)&7 == r0&7
    const int selem = seg * 8;

    // ldmatrix lane geometry
    const int mi = lane >> 3;
    const int a_row = (lane & 7) + ((mi & 1) << 3);
    const int akb4  = (mi >= 2) ? 1 : 0;
    const int b_row = (lane & 7) + ((mi >= 2) ? 8 : 0);
    const int bkb4  = (mi & 1) ? 1 : 0;
    const int arsw  = a_row & 7;
    const int brsw  = b_row & 7;

    float acc[4][4][4];
#pragma unroll
    for (int i = 0; i < 4; i++)
#pragma unroll
        for (int j = 0; j < 4; j++)
#pragma unroll
            for (int u = 0; u < 4; u++) acc[i][j][u] = 0.f;

    auto load_chunk = [&](int ch, int stg) {
        const int k0 = ch * KCH2;
        const uint32_t base = sb + stg * STAGE_B;
#pragma unroll
        for (int j = 0; j < 4; j++) {
            const int row = r0 + j * 32;
            const uint32_t d = (uint32_t)(row * 128) + sw;
            CPASYNC16(base + 0 * OPB + d, g_vh + (size_t)(bm + row) * D_IN + k0 + selem);
            CPASYNC16(base + 1 * OPB + d, g_wh + (size_t)(bn + row) * D_IN + k0 + selem);
        }
    };

    load_chunk(0, 0);
    asm volatile("cp.async.commit_group;");
    load_chunk(1, 1);
    asm volatile("cp.async.commit_group;");

    for (int ch = 0; ch < NCHUNK; ch++) {
        if (ch < NCHUNK - 1) {
            asm volatile("cp.async.wait_group 1;");
        } else {
            asm volatile("cp.async.wait_group 0;");
        }
        __syncthreads();

        if (ch + 2 < NCHUNK) {
            load_chunk(ch + 2, (ch + 2) % NSTAGE);
            asm volatile("cp.async.commit_group;");
        }

        const uint32_t stgb  = sb + (ch % NSTAGE) * STAGE_B;
        const uint32_t aBase = stgb + 0 * OPB + (uint32_t)((wm * 64 + a_row) * 128);
        const uint32_t bBase = stgb + 1 * OPB + (uint32_t)((wn * 32 + b_row) * 128);

#pragma unroll
        for (int kt = 0; kt < 4; kt++) {
            const uint32_t aoff = (uint32_t)(((kt * 2 + akb4) ^ arsw) << 4);
            const uint32_t boff = (uint32_t)(((kt * 2 + bkb4) ^ brsw) << 4);
            uint32_t ah[4][4], bh[2][4];
#pragma unroll
            for (int mt = 0; mt < 4; mt++)
                ldsm_x4(ah[mt], aBase + mt * 2048 + aoff);
#pragma unroll
            for (int h = 0; h < 2; h++)
                ldsm_x4(bh[h], bBase + h * 2048 + boff);
#pragma unroll
            for (int mt = 0; mt < 4; mt++)
#pragma unroll
                for (int nt = 0; nt < 4; nt++)
                    mma_f16(acc[mt][nt], ah[mt], bh[nt >> 1][(nt & 1) * 2], bh[nt >> 1][(nt & 1) * 2 + 1]);
        }
    }
    __syncthreads();

    // Epilogue: bias + silu -> half stage [row][136] -> coalesced g_Hh rows
    {
        __half* stg = (__half*)smem;
        const float* bias = (const float*)(smem + SMO_BIAS);
#pragma unroll
        for (int mt = 0; mt < 4; mt++) {
#pragma unroll
            for (int nt = 0; nt < 4; nt++) {
                int r = wm * 64 + mt * 16 + (lane >> 2);
                int c0 = wn * 32 + nt * 8 + 2 * (lane & 3);
                float b0 = bias[c0], b1 = bias[c0 + 1];
                float y0 = silu_f(acc[mt][nt][0] + b0);
                float y1 = silu_f(acc[mt][nt][1] + b1);
                float y2 = silu_f(acc[mt][nt][2] + b0);
                float y3 = silu_f(acc[mt][nt][3] + b1);
                *(__half2*)(stg + r * 136 + c0)       = __floats2half2_rn(y0, y1);
                *(__half2*)(stg + (r + 8) * 136 + c0) = __floats2half2_rn(y2, y3);
            }
        }
        __syncthreads();
#pragma unroll
        for (int k = 0; k < 8; k++) {
            int lin = tid + k * 256;    // 0..2047
            int row = lin >> 4, s = lin & 15;
            uint4 val = *(uint4*)((char*)smem + row * 272 + s * 16);
            *(uint4*)(g_Hh + (size_t)(bm + row) * NCATP + bn + s * 8) = val;
        }
    }
}

// ---------------------------------------------------------------------------
// Kernel: tail7 — tensor-core tail. grid (B/128, 3), 256 threads (8 warps).
// (verbatim from R15 — validated at ~25us-class)
// ---------------------------------------------------------------------------
#define A7      0
#define H27     32768
#define W27     53248
#define W37     63488
#define ZAC7    72704
#define WG7     107520
#define PB2     108544
#define PB3     108800
#define PGM     109312
#define PBT     109824
#define PGW     110336
#define PGB     110592
#define T7_SMEM 110600

__global__ void __launch_bounds__(256, 2) tail7_kernel(
    const float* __restrict__ sw2, const float* __restrict__ sb2,
    const float* __restrict__ sw3, const float* __restrict__ sb3,
    const float* __restrict__ sgam, const float* __restrict__ sbet,
    const float* __restrict__ sgw2, const float* __restrict__ sgb2,
    const float* __restrict__ gw2, const float* __restrict__ gb2,
    const float* __restrict__ gw3, const float* __restrict__ gb3,
    const float* __restrict__ ggam, const float* __restrict__ gbet,
    const float* __restrict__ ggw2, const float* __restrict__ ggb2,
    float* __restrict__ out) {
    extern __shared__ char smem[];
    const uint32_t sb = smem_u32(smem);
    const int tid  = threadIdx.x;
    const int lane = tid & 31;
    const int warp = tid >> 5;
    const int ws = warp >> 2;
    const int wr = warp & 3;
    const int p  = blockIdx.y;
    const int t0 = blockIdx.x * 128;
    const int e_base = (p == 2) ? 0 : ((p == 0) ? 2 : 4);
    const int gslot  = (p == 2) ? 0 : (p + 1);

    {
        const __half* src = g_Hh + (size_t)t0 * NCATP + e_base * 64;
#pragma unroll
        for (int k = 0; k < 8; k++) {
            int lin = tid + k * 256;
            int row = lin >> 4, s = lin & 15;
            uint4 val = *(const uint4*)(src + (size_t)row * NCATP + s * 8);
            *(uint4*)(smem + A7 + row * 256 + ((s ^ (row & 7)) << 4)) = val;
        }
    }
#pragma unroll
    for (int s = 0; s < 2; s++) {
        const int e = e_base + s;
        const float* w2src = (e < 2) ? (sw2 + (size_t)e * 2048) : (gw2 + (size_t)(e - 2) * 2048);
        const float* w3src = (e < 2) ? (sw3 + (size_t)e * 2048) : (gw3 + (size_t)(e - 2) * 2048);
        __half* w2d = (__half*)(smem + W27 + s * 5120);
        __half* w3d = (__half*)(smem + W37 + s * 4608);
        for (int i = tid; i < 2048; i += 256) {
            w2d[(i >> 5) * 40 + (i & 31)] = __float2half_rn(w2src[i]);
            w3d[(i >> 6) * 72 + (i & 63)] = __float2half_rn(w3src[i]);
        }
        if (tid < H2) ((float*)(smem + PB2))[s * 32 + tid] =
            (e < 2) ? sb2[e * 32 + tid] : gb2[(e - 2) * 32 + tid];
        if (tid < D_OUT) {
            ((float*)(smem + PB3))[s * 64 + tid] = (e < 2) ? sb3[e * 64 + tid]  : gb3[(e - 2) * 64 + tid];
            ((float*)(smem + PGM))[s * 64 + tid] = (e < 2) ? sgam[e * 64 + tid] : ggam[(e - 2) * 64 + tid];
            ((float*)(smem + PBT))[s * 64 + tid] = (e < 2) ? sbet[e * 64 + tid] : gbet[(e - 2) * 64 + tid];
        }
    }
    if (tid < 64) ((float*)(smem + PGW))[tid] = (gslot == 0) ? sgw2[tid] : ggw2[(gslot - 1) * 64 + tid];
    if (tid < 2)  ((float*)(smem + PGB))[tid] = (gslot == 0) ? sgb2[tid] : ggb2[(gslot - 1) * 2 + tid];
    __syncthreads();

    if (tid < 128) {
        const __half2* gp = (const __half2*)(g_Hh + (size_t)(t0 + tid) * NCATP + 384 + gslot * 32);
        const float* gw = (const float*)(smem + PGW);
        float l0 = ((const float*)(smem + PGB))[0];
        float l1 = ((const float*)(smem + PGB))[1];
#pragma unroll
        for (int i = 0; i < 16; i++) {
            float2 h = __half22float2(gp[i]);
            l0 += h.x * gw[(2 * i) * 2]     + h.y * gw[(2 * i + 1) * 2];
            l1 += h.x * gw[(2 * i) * 2 + 1] + h.y * gw[(2 * i + 1) * 2 + 1];
        }
        float mx = fmaxf(l0, l1);
        float ea = __expf(l0 - mx), eb = __expf(l1 - mx);
        float inv = 1.f / (ea + eb);
        ((float2*)(smem + WG7))[tid] = make_float2(ea * inv, eb * inv);
    }

    const int mi = lane >> 3;
    const int a_row = (lane & 7) + ((mi & 1) << 3);
    const int akb = (mi >= 2) ? 1 : 0;
    const int tokb = wr * 32;

    float c2[2][4][4];
#pragma unroll
    for (int i = 0; i < 2; i++)
#pragma unroll
        for (int j = 0; j < 4; j++)
#pragma unroll
            for (int u = 0; u < 4; u++) c2[i][j][u] = 0.f;
    {
        const uint32_t aA = sb + A7 + (uint32_t)((tokb + a_row) * 256);
        const uint32_t bA = sb + W27 + (uint32_t)(ws * 5120 + (lane & 15) * 80);
#pragma unroll
        for (int kt = 0; kt < 4; kt++) {
            uint32_t aseg = (uint32_t)(((ws * 8 + kt * 2 + akb) ^ (lane & 7)) << 4);
            uint32_t a0[4], a1[4];
            ldsm_x4(a0, aA + aseg);
            ldsm_x4(a1, aA + 4096 + aseg);
#pragma unroll
            for (int nt = 0; nt < 4; nt++) {
                uint32_t b[2];
                ldsm_x2t(b, bA + (uint32_t)(kt * 16 * 80 + nt * 16));
                mma_f16(c2[0][nt], a0, b[0], b[1]);
                mma_f16(c2[1][nt], a1, b[0], b[1]);
            }
        }
    }
    {
        const float* b2v = (const float*)(smem + PB2) + ws * 32;
        char* h2b = smem + H27 + ws * 10240;
#pragma unroll
        for (int mt = 0; mt < 2; mt++)
#pragma unroll
            for (int nt = 0; nt < 4; nt++) {
                int c0 = nt * 8 + 2 * (lane & 3);
                int r  = tokb + mt * 16 + (lane >> 2);
                float b0 = b2v[c0], b1 = b2v[c0 + 1];
                float y0 = silu_f(c2[mt][nt][0] + b0);
                float y1 = silu_f(c2[mt][nt][1] + b1);
                float y2 = silu_f(c2[mt][nt][2] + b0);
                float y3 = silu_f(c2[mt][nt][3] + b1);
                *(__half2*)(h2b + r * 80 + c0 * 2)       = __floats2half2_rn(y0, y1);
                *(__half2*)(h2b + (r + 8) * 80 + c0 * 2) = __floats2half2_rn(y2, y3);
            }
    }
    __syncthreads();

    float c3[2][8][4];
#pragma unroll
    for (int i = 0; i < 2; i++)
#pragma unroll
        for (int j = 0; j < 8; j++)
#pragma unroll
            for (int u = 0; u < 4; u++) c3[i][j][u] = 0.f;
    {
        const uint32_t aA = sb + H27 + (uint32_t)(ws * 10240 + (tokb + a_row) * 80);
        const uint32_t bA = sb + W37 + (uint32_t)(ws * 4608 + (lane & 15) * 144);
#pragma unroll
        for (int kt = 0; kt < 2; kt++) {
            uint32_t aoff = (uint32_t)(kt * 32 + akb * 16);
            uint32_t a0[4], a1[4];
            ldsm_x4(a0, aA + aoff);
            ldsm_x4(a1, aA + 16 * 80 + aoff);
#pragma unroll
            for (int nt = 0; nt < 8; nt++) {
                uint32_t b[2];
                ldsm_x2t(b, bA + (uint32_t)(kt * 16 * 144 + nt * 16));
                mma_f16(c3[0][nt], a0, b[0], b[1]);
                mma_f16(c3[1][nt], a1, b[0], b[1]);
            }
        }
    }

    const float* b3v = (const float*)(smem + PB3) + ws * 64;
    const float* gmv = (const float*)(smem + PGM) + ws * 64;
    const float* btv = (const float*)(smem + PBT) + ws * 64;
    const unsigned FULL = 0xffffffffu;

    auto ln_acc = [&](bool add) {
#pragma unroll
        for (int mt = 0; mt < 2; mt++)
#pragma unroll
            for (int rh = 0; rh < 2; rh++) {
                float s1 = 0.f;
#pragma unroll
                for (int nt = 0; nt < 8; nt++) {
                    int c0 = nt * 8 + 2 * (lane & 3);
                    float v0 = c3[mt][nt][rh * 2]     + b3v[c0];
                    float v1 = c3[mt][nt][rh * 2 + 1] + b3v[c0 + 1];
                    s1 += v0 + v1;
                }
                s1 += __shfl_xor_sync(FULL, s1, 1);
                s1 += __shfl_xor_sync(FULL, s1, 2);
                float mu = s1 * (1.f / 64.f);
                float s2 = 0.f;
#pragma unroll
                for (int nt = 0; nt < 8; nt++) {
                    int c0 = nt * 8 + 2 * (lane & 3);
                    float d0 = c3[mt][nt][rh * 2]     + b3v[c0]     - mu;
                    float d1 = c3[mt][nt][rh * 2 + 1] + b3v[c0 + 1] - mu;
                    s2 += d0 * d0 + d1 * d1;
                }
                s2 += __shfl_xor_sync(FULL, s2, 1);
                s2 += __shfl_xor_sync(FULL, s2, 2);
                float x = s2 * (1.f / 64.f) + LN_EPS;
                float rinv = rsqrtf(x);
                rinv = rinv * (1.5f - 0.5f * x * rinv * rinv);

                int row = tokb + mt * 16 + (lane >> 2) + rh * 8;
                float wg = ((const float*)(smem + WG7))[row * 2 + ws];
                float* zr = (float*)(smem + ZAC7) + row * 68;
#pragma unroll
                for (int nt = 0; nt < 8; nt++) {
                    int c0 = nt * 8 + 2 * (lane & 3);
                    float d0 = c3[mt][nt][rh * 2]     + b3v[c0]     - mu;
                    float d1 = c3[mt][nt][rh * 2 + 1] + b3v[c0 + 1] - mu;
                    float z0 = wg * (gmv[c0] * d0 * rinv + btv[c0]);
                    float z1 = wg * (gmv[c0 + 1] * d1 * rinv + btv[c0 + 1]);
                    if (add) { zr[c0] += z0; zr[c0 + 1] += z1; }
                    else     { zr[c0]  = z0; zr[c0 + 1]  = z1; }
                }
            }
    };

    if (ws == 0) ln_acc(false);
    __syncthreads();
    if (ws == 1) ln_acc(true);
    __syncthreads();

    float* ob = out + ((size_t)p * B_TOK + t0) * D_OUT;
#pragma unroll
    for (int k = 0; k < 8; k++) {
        int lin = tid + k * 256;
        int row = lin >> 4, c4 = (lin & 15) * 4;
        float4 v = *(float4*)((float*)(smem + ZAC7) + row * 68 + c4);
        *(float4*)(ob + (size_t)row * D_OUT + c4) = v;
    }
}

// ---------------------------------------------------------------------------
// Launch
// ---------------------------------------------------------------------------
extern "C" void kernel_launch(void* const* d_in, const int* in_sizes, int n_in,
                              void* d_out, int out_size) {
    (void)in_sizes; (void)n_in; (void)out_size;
    const float* v    = (const float*)d_in[0];
    const float* sw1  = (const float*)d_in[1];
    const float* sb1  = (const float*)d_in[2];
    const float* sw2  = (const float*)d_in[3];
    const float* sb2  = (const float*)d_in[4];
    const float* sw3  = (const float*)d_in[5];
    const float* sb3  = (const float*)d_in[6];
    const float* sgam = (const float*)d_in[7];
    const float* sbet = (const float*)d_in[8];
    const float* sgw1 = (const float*)d_in[9];
    const float* sgb1 = (const float*)d_in[10];
    const float* sgw2 = (const float*)d_in[11];
    const float* sgb2 = (const float*)d_in[12];
    const float* gw1  = (const float*)d_in[13];
    const float* gb1  = (const float*)d_in[14];
    const float* gw2  = (const float*)d_in[15];
    const float* gb2  = (const float*)d_in[16];
    const float* gw3  = (const float*)d_in[17];
    const float* gb3  = (const float*)d_in[18];
    const float* ggam = (const float*)d_in[19];
    const float* gbet = (const float*)d_in[20];
    const float* ggw1 = (const float*)d_in[21];
    const float* ggb1 = (const float*)d_in[22];
    const float* ggw2 = (const float*)d_in[23];
    const float* ggb2 = (const float*)d_in[24];
    float* out = (float*)d_out;

    prep_kernel<<<CONV_BLOCKS + 256, 256>>>(
        v, sw1, sb1, gw1, gb1, sgw1, sgb1, ggw1, ggb1);

    cudaFuncSetAttribute(gemm1_mma_kernel, cudaFuncAttributeMaxDynamicSharedMemorySize, GEMM_SMEM);
    dim3 g1(NCATP / 128, B_TOK / 128);
    gemm1_mma_kernel<<<g1, 256, GEMM_SMEM>>>();

    cudaFuncSetAttribute(tail7_kernel, cudaFuncAttributeMaxDynamicSharedMemorySize, T7_SMEM);
    dim3 g2(B_TOK / 128, 3);
    tail7_kernel<<<g2, 256, T7_SMEM>>>(sw2, sb2, sw3, sb3, sgam, sbet, sgw2, sgb2,
                                       gw2, gb2, gw3, gb3, ggam, gbet, ggw2, ggb2, out);
}